// round 13
// baseline (speedup 1.0000x reference)
#include <cuda_runtime.h>
#include <cuda_bf16.h>
#include <cuda_fp16.h>

#define DIMN 1024
#define NB 16
#define MATS ((size_t)DIMN * DIMN)     /* 1M  */
#define TOT  ((size_t)NB * MATS)       /* 16M */

// ---------------- scratch (device globals; allocation-free) ----------------
__device__ __nv_bfloat16 g_a1h[TOT],  g_a1l[TOT];     // bf16 row-major (S GEMM A)
__device__ __nv_bfloat16 g_a2h[TOT],  g_a2l[TOT];     // bf16 row-major (a2p GEMM A)
__device__ __nv_bfloat16 g_gwh[MATS], g_gwl[MATS];
__device__ __nv_bfloat16 g_a2ph[TOT], g_a2pl[TOT];    // bf16 (S GEMM B)
__device__ float         g_S[TOT];
__device__ __half g_A1h[TOT],  g_A1l[TOT];     // fp16 rowsoftmax(S), lo*512
__device__ __half g_A2h[TOT],  g_A2l[TOT];     // fp16 colsoftmax(S)^T, lo*512
__device__ __half g_a2Th[TOT], g_a2Tl[TOT];    // fp16 a2^T, lo*512
__device__ __half g_a1Th[TOT], g_a1Tl[TOT];    // fp16 a1^T, lo*512
__device__ float g_rmax[NB * DIMN], g_rinv[NB * DIMN];
__device__ float g_cmax[NB * DIMN], g_cinv[NB * DIMN];
__device__ float g_rpm[NB * 8 * DIMN], g_rps[NB * 8 * DIMN];
__device__ float g_cpm[NB * 8 * DIMN], g_cps[NB * 8 * DIMN];

// ---------------- helpers ----------------
__device__ __forceinline__ unsigned smem_u32(const void* p) {
    unsigned r;
    asm("{ .reg .u64 t; cvta.to.shared.u64 t, %1; cvt.u32.u64 %0, t; }"
        : "=r"(r) : "l"(p));
    return r;
}
__device__ __forceinline__ unsigned swz64(unsigned x) { return x ^ ((x >> 3) & 0x30); }

__device__ __forceinline__ void bsplit(float v, __nv_bfloat16& h, __nv_bfloat16& l) {
    h = __float2bfloat16_rn(v);
    l = __float2bfloat16_rn(v - __bfloat162float(h));
}
__device__ __forceinline__ void hsplit(float v, __half& h, __half& l) {
    h = __float2half_rn(v);
    l = __float2half_rn((v - __half2float(h)) * 512.0f);
}

#define CP16(dst, src) \
    asm volatile("cp.async.cg.shared.global [%0], [%1], 16;" :: "r"(dst), "l"(src))

#define LDSM4(r, addr) \
    asm volatile("ldmatrix.sync.aligned.m8n8.x4.shared.b16 {%0,%1,%2,%3}, [%4];" \
        : "=r"((r)[0]), "=r"((r)[1]), "=r"((r)[2]), "=r"((r)[3]) : "r"(addr))

#define MMA16816(c, a, b)                                                      \
    asm volatile("mma.sync.aligned.m16n8k16.row.col.f32.bf16.bf16.f32 "        \
        "{%0,%1,%2,%3}, {%4,%5,%6,%7}, {%8,%9}, {%0,%1,%2,%3};"                \
        : "+f"((c)[0]), "+f"((c)[1]), "+f"((c)[2]), "+f"((c)[3])               \
        : "r"((a)[0]), "r"((a)[1]), "r"((a)[2]), "r"((a)[3]),                  \
          "r"((b)[0]), "r"((b)[1]))

#define MMAH32(c, a, b)                                                        \
    asm volatile("mma.sync.aligned.m16n8k16.row.col.f32.f16.f16.f32 "          \
        "{%0,%1,%2,%3}, {%4,%5,%6,%7}, {%8,%9}, {%0,%1,%2,%3};"                \
        : "+f"((c)[0]), "+f"((c)[1]), "+f"((c)[2]), "+f"((c)[3])               \
        : "r"((a)[0]), "r"((a)[1]), "r"((a)[2]), "r"((a)[3]),                  \
          "r"((b)[0]), "r"((b)[1]))

#define MMAH16(c, a, b)                                                        \
    asm volatile("mma.sync.aligned.m16n8k16.row.col.f16.f16.f16.f16 "          \
        "{%0,%1}, {%2,%3,%4,%5}, {%6,%7}, {%0,%1};"                            \
        : "+r"((c)[0]), "+r"((c)[1])                                           \
        : "r"((a)[0]), "r"((a)[1]), "r"((a)[2]), "r"((a)[3]),                  \
          "r"((b)[0]), "r"((b)[1]))

// ================= GEMM cores: CTA 128x128, BK=32, 3-stage, 256 thr =======
#define STAGE_B   32768
#define SMEM_TOT  (3 * STAGE_B)

struct GPtr { const char *ah, *al, *bh, *bl; };

__device__ __forceinline__ void issue_loads_s(unsigned st, const GPtr& p, unsigned kbyte,
                                              unsigned so0, unsigned so1) {
    const unsigned RS = 64u * DIMN * 2u;
    CP16(st +     0 + so0, p.ah + kbyte);
    CP16(st +     0 + so1, p.ah + kbyte + RS);
    CP16(st +  8192 + so0, p.al + kbyte);
    CP16(st +  8192 + so1, p.al + kbyte + RS);
    CP16(st + 16384 + so0, p.bh + kbyte);
    CP16(st + 16384 + so1, p.bh + kbyte + RS);
    CP16(st + 24576 + so0, p.bl + kbyte);
    CP16(st + 24576 + so1, p.bl + kbyte + RS);
    asm volatile("cp.async.commit_group;" ::: "memory");
}

// bf16 3-term mainloop (a2p, S)
__device__ __forceinline__ void mainloop_s(unsigned sb, const GPtr& p,
                                           unsigned so0, unsigned so1,
                                           int lane, int wm, int wn,
                                           float (*acc)[4][4])
{
    issue_loads_s(sb,           p, 0,  so0, so1);
    issue_loads_s(sb + STAGE_B, p, 64, so0, so1);

#pragma unroll 1
    for (int it = 0; it < 32; it++) {
        if (it < 31) asm volatile("cp.async.wait_group 1;" ::: "memory");
        else         asm volatile("cp.async.wait_group 0;" ::: "memory");
        __syncthreads();
        if (it + 2 < 32) {
            unsigned wst = sb + (unsigned)((it + 2) % 3) * STAGE_B;
            issue_loads_s(wst, p, (unsigned)(it + 2) * 64, so0, so1);
        }
        const unsigned st = sb + (unsigned)(it % 3) * STAGE_B;

#pragma unroll
        for (int ks = 0; ks < 2; ks++) {
            const unsigned kb = ks * 32;
            unsigned bh[8], bl[8];
#pragma unroll
            for (int nt = 0; nt < 2; nt++) {
                unsigned brow = wn + nt * 16 + (lane & 7) + ((lane >> 4) & 1) * 8;
                unsigned bb   = kb + ((lane >> 3) & 1) * 16;
                unsigned ba   = st + 16384 + swz64(brow * 64 + bb);
                LDSM4(bh + nt * 4, ba);
                LDSM4(bl + nt * 4, ba + 8192);
            }
#pragma unroll
            for (int mf = 0; mf < 4; mf++) {
                unsigned arow = wm + mf * 16 + (lane & 15);
                unsigned ab   = kb + ((lane >> 4) & 1) * 16;
                unsigned aa   = st + swz64(arow * 64 + ab);
                unsigned ah[4], al[4];
                LDSM4(ah, aa);
                LDSM4(al, aa + 8192);
#pragma unroll
                for (int nf = 0; nf < 4; nf++) {
                    MMA16816(acc[mf][nf], ah, bh + nf * 2);
                    MMA16816(acc[mf][nf], ah, bl + nf * 2);
                    MMA16816(acc[mf][nf], al, bh + nf * 2);
                }
            }
        }
    }
}

// fp16 mainloop (dual): hi*hi f32acc + cross f16acc (lo pre-scaled x512)
__device__ __forceinline__ void mainloop_h(unsigned sb, const GPtr& p,
                                           unsigned so0, unsigned so1,
                                           int lane, int wm, int wn,
                                           float (*acc)[4][4], unsigned (*accC)[4][2])
{
    issue_loads_s(sb,           p, 0,  so0, so1);
    issue_loads_s(sb + STAGE_B, p, 64, so0, so1);

#pragma unroll 1
    for (int it = 0; it < 32; it++) {
        if (it < 31) asm volatile("cp.async.wait_group 1;" ::: "memory");
        else         asm volatile("cp.async.wait_group 0;" ::: "memory");
        __syncthreads();
        if (it + 2 < 32) {
            unsigned wst = sb + (unsigned)((it + 2) % 3) * STAGE_B;
            issue_loads_s(wst, p, (unsigned)(it + 2) * 64, so0, so1);
        }
        const unsigned st = sb + (unsigned)(it % 3) * STAGE_B;

#pragma unroll
        for (int ks = 0; ks < 2; ks++) {
            const unsigned kb = ks * 32;
            unsigned bh[8], bl[8];
#pragma unroll
            for (int nt = 0; nt < 2; nt++) {
                unsigned brow = wn + nt * 16 + (lane & 7) + ((lane >> 4) & 1) * 8;
                unsigned bb   = kb + ((lane >> 3) & 1) * 16;
                unsigned ba   = st + 16384 + swz64(brow * 64 + bb);
                LDSM4(bh + nt * 4, ba);
                LDSM4(bl + nt * 4, ba + 8192);
            }
#pragma unroll
            for (int mf = 0; mf < 4; mf++) {
                unsigned arow = wm + mf * 16 + (lane & 15);
                unsigned ab   = kb + ((lane >> 4) & 1) * 16;
                unsigned aa   = st + swz64(arow * 64 + ab);
                unsigned ah[4], al[4];
                LDSM4(ah, aa);
                LDSM4(al, aa + 8192);
#pragma unroll
                for (int nf = 0; nf < 4; nf++) {
                    MMAH32(acc[mf][nf], ah, bh + nf * 2);       // hi*hi, f32 acc
                    MMAH16(accC[mf][nf], ah, bl + nf * 2);      // hi*(lo*512), f16 acc
                    MMAH16(accC[mf][nf], al, bh + nf * 2);      // (lo*512)*hi, f16 acc
                }
            }
        }
    }
}

__device__ __forceinline__ void make_gptr(GPtr& p, unsigned& so0, unsigned& so1,
    const void* Ah, const void* Al, const void* Bh, const void* Bl,
    size_t zA, size_t zB, size_t row0, size_t col0, int tid)
{
    size_t ar = row0 + (tid >> 2);
    size_t br = col0 + (tid >> 2);
    size_t ko = (size_t)(tid & 3) * 8;
    p.ah = (const char*)Ah + (zA + ar * DIMN + ko) * 2;
    p.al = (const char*)Al + (zA + ar * DIMN + ko) * 2;
    p.bh = (const char*)Bh + (zB + br * DIMN + ko) * 2;
    p.bl = (const char*)Bl + (zB + br * DIMN + ko) * 2;
    so0 = swz64(((unsigned)(tid >> 2)) * 64 + (tid & 3) * 16);
    so1 = so0 + 4096;
}

// ---- a2p GEMM: bias add + split bf16 pair out ----
__global__ __launch_bounds__(256, 2)
void gemm_a2p(const __nv_bfloat16* __restrict__ Ah, const __nv_bfloat16* __restrict__ Al,
              const __nv_bfloat16* __restrict__ Bh, const __nv_bfloat16* __restrict__ Bl,
              __nv_bfloat16* __restrict__ outH, __nv_bfloat16* __restrict__ outL,
              const float* __restrict__ bias)
{
    extern __shared__ char smem[];
    const unsigned sb = smem_u32(smem);
    const int tid = threadIdx.x, warp = tid >> 5, lane = tid & 31;
    const int wm = (warp >> 2) * 64, wn = (warp & 3) * 32;
    const size_t row0 = (size_t)blockIdx.y * 128, col0 = (size_t)blockIdx.x * 128;

    GPtr p; unsigned so0, so1;
    make_gptr(p, so0, so1, Ah, Al, Bh, Bl, 0, 0, row0, col0, tid);
    float acc[4][4][4] = {};
    mainloop_s(sb, p, so0, so1, lane, wm, wn, acc);

    const int g = lane >> 2, t = lane & 3;
#pragma unroll
    for (int mf = 0; mf < 4; mf++)
#pragma unroll
        for (int nf = 0; nf < 4; nf++) {
            const float* c = acc[mf][nf];
            size_t r0 = row0 + wm + mf * 16 + g;
            size_t cc = col0 + wn + nf * 8 + 2 * t;
            float b0 = bias[cc], b1 = bias[cc + 1];
            union { __nv_bfloat16 b[2]; unsigned u; } H0, L0, H1, L1;
            bsplit(c[0] + b0, H0.b[0], L0.b[0]);
            bsplit(c[1] + b1, H0.b[1], L0.b[1]);
            bsplit(c[2] + b0, H1.b[0], L1.b[0]);
            bsplit(c[3] + b1, H1.b[1], L1.b[1]);
            *(unsigned*)(outH + r0 * DIMN + cc)       = H0.u;
            *(unsigned*)(outL + r0 * DIMN + cc)       = L0.u;
            *(unsigned*)(outH + (r0 + 8) * DIMN + cc) = H1.u;
            *(unsigned*)(outL + (r0 + 8) * DIMN + cc) = L1.u;
        }
}

// ---- S GEMM: fp32 out + fused per-CTA row/col softmax partials ----
__global__ __launch_bounds__(256, 2)
void gemm_S(const __nv_bfloat16* __restrict__ Ah, const __nv_bfloat16* __restrict__ Al,
            const __nv_bfloat16* __restrict__ Bh, const __nv_bfloat16* __restrict__ Bl,
            float* __restrict__ outF,
            float* __restrict__ rpm, float* __restrict__ rps,
            float* __restrict__ cpm, float* __restrict__ cps)
{
    extern __shared__ char smem[];
    const unsigned sb = smem_u32(smem);
    const int tid = threadIdx.x, warp = tid >> 5, lane = tid & 31;
    const int wm = (warp >> 2) * 64, wn = (warp & 3) * 32;
    const size_t z = blockIdx.z;
    const size_t row0 = (size_t)blockIdx.y * 128, col0 = (size_t)blockIdx.x * 128;

    GPtr p; unsigned so0, so1;
    make_gptr(p, so0, so1, Ah, Al, Bh, Bl, z * MATS, z * MATS, row0, col0, tid);
    float acc[4][4][4] = {};
    mainloop_s(sb, p, so0, so1, lane, wm, wn, acc);

    const int g = lane >> 2, t = lane & 3;
    float* outb = outF + z * MATS;
#pragma unroll
    for (int mf = 0; mf < 4; mf++)
#pragma unroll
        for (int nf = 0; nf < 4; nf++) {
            const float* c = acc[mf][nf];
            size_t r0 = row0 + wm + mf * 16 + g;
            size_t cc = col0 + wn + nf * 8 + 2 * t;
            *(float2*)(outb + r0 * DIMN + cc)       = make_float2(c[0], c[1]);
            *(float2*)(outb + (r0 + 8) * DIMN + cc) = make_float2(c[2], c[3]);
        }

    // ---- softmax partials from registers ----
    float rm_[4][2], rs_[4][2];
#pragma unroll
    for (int mf = 0; mf < 4; mf++)
#pragma unroll
        for (int rh = 0; rh < 2; rh++) {
            float m = -1e30f;
#pragma unroll
            for (int nf = 0; nf < 4; nf++)
                m = fmaxf(m, fmaxf(acc[mf][nf][rh * 2], acc[mf][nf][rh * 2 + 1]));
            m = fmaxf(m, __shfl_xor_sync(0xffffffffu, m, 1));
            m = fmaxf(m, __shfl_xor_sync(0xffffffffu, m, 2));
            float s = 0.f;
#pragma unroll
            for (int nf = 0; nf < 4; nf++)
                s += __expf(acc[mf][nf][rh * 2] - m) + __expf(acc[mf][nf][rh * 2 + 1] - m);
            s += __shfl_xor_sync(0xffffffffu, s, 1);
            s += __shfl_xor_sync(0xffffffffu, s, 2);
            rm_[mf][rh] = m; rs_[mf][rh] = s;
        }
    float cm_[4][2], cs_[4][2];
#pragma unroll
    for (int nf = 0; nf < 4; nf++)
#pragma unroll
        for (int cr = 0; cr < 2; cr++) {
            float m = -1e30f;
#pragma unroll
            for (int mf = 0; mf < 4; mf++)
                m = fmaxf(m, fmaxf(acc[mf][nf][cr], acc[mf][nf][2 + cr]));
            m = fmaxf(m, __shfl_xor_sync(0xffffffffu, m, 4));
            m = fmaxf(m, __shfl_xor_sync(0xffffffffu, m, 8));
            m = fmaxf(m, __shfl_xor_sync(0xffffffffu, m, 16));
            float s = 0.f;
#pragma unroll
            for (int mf = 0; mf < 4; mf++)
                s += __expf(acc[mf][nf][cr] - m) + __expf(acc[mf][nf][2 + cr] - m);
            s += __shfl_xor_sync(0xffffffffu, s, 4);
            s += __shfl_xor_sync(0xffffffffu, s, 8);
            s += __shfl_xor_sync(0xffffffffu, s, 16);
            cm_[nf][cr] = m; cs_[nf][cr] = s;
        }

    __syncthreads();   // stage buffers dead; reuse smem for staging
    float* sRM = (float*)smem;        // [4][128]
    float* sRS = sRM + 512;
    float* sCM = sRS + 512;           // [2][128]
    float* sCS = sCM + 256;
    if (t == 0) {
#pragma unroll
        for (int mf = 0; mf < 4; mf++)
#pragma unroll
            for (int rh = 0; rh < 2; rh++) {
                int r = wm + mf * 16 + g + 8 * rh;
                sRM[(warp & 3) * 128 + r] = rm_[mf][rh];
                sRS[(warp & 3) * 128 + r] = rs_[mf][rh];
            }
    }
    if (g == 0) {
#pragma unroll
        for (int nf = 0; nf < 4; nf++)
#pragma unroll
            for (int cr = 0; cr < 2; cr++) {
                int c = wn + nf * 8 + 2 * t + cr;
                sCM[(warp >> 2) * 128 + c] = cm_[nf][cr];
                sCS[(warp >> 2) * 128 + c] = cs_[nf][cr];
            }
    }
    __syncthreads();
    if (tid < 128) {
        int r = tid;
        float m = -1e30f;
#pragma unroll
        for (int w = 0; w < 4; w++) m = fmaxf(m, sRM[w * 128 + r]);
        float s = 0.f;
#pragma unroll
        for (int w = 0; w < 4; w++) s += sRS[w * 128 + r] * __expf(sRM[w * 128 + r] - m);
        size_t ri = (z * DIMN + row0 + r) * 8 + blockIdx.x;
        rpm[ri] = m; rps[ri] = s;

        int c = tid;
        float mc = fmaxf(sCM[c], sCM[128 + c]);
        float sc = sCS[c] * __expf(sCM[c] - mc) + sCS[128 + c] * __expf(sCM[128 + c] - mc);
        size_t ci = (z * DIMN + col0 + c) * 8 + blockIdx.y;
        cpm[ci] = mc; cps[ci] = sc;
    }
}

// ---- merged M1/M2 GEMM (fp16): grid z in [0,8), sel = z>>2 ----
__global__ __launch_bounds__(256, 2)
void gemm_dual(const __half* __restrict__ A1h, const __half* __restrict__ A1l,
               const __half* __restrict__ B1h, const __half* __restrict__ B1l,
               float* __restrict__ o1,
               const __half* __restrict__ A2h, const __half* __restrict__ A2l,
               const __half* __restrict__ B2h, const __half* __restrict__ B2l,
               float* __restrict__ o2)
{
    extern __shared__ char smem[];
    const unsigned sb = smem_u32(smem);
    const int tid = threadIdx.x, warp = tid >> 5, lane = tid & 31;
    const int wm = (warp >> 2) * 64, wn = (warp & 3) * 32;
    const int sel = blockIdx.z >> 2;
    const size_t z = blockIdx.z & 3;
    const size_t row0 = (size_t)blockIdx.y * 128, col0 = (size_t)blockIdx.x * 128;

    const __half* Ah = sel ? A2h : A1h;
    const __half* Al = sel ? A2l : A1l;
    const __half* Bh = sel ? B2h : B1h;
    const __half* Bl = sel ? B2l : B1l;
    float* outF = sel ? o2 : o1;

    GPtr p; unsigned so0, so1;
    make_gptr(p, so0, so1, Ah, Al, Bh, Bl, z * MATS, z * MATS, row0, col0, tid);
    float acc[4][4][4] = {};
    unsigned accC[4][4][2] = {};
    mainloop_h(sb, p, so0, so1, lane, wm, wn, acc, accC);

    const int g = lane >> 2, t = lane & 3;
    float* outb = outF + z * MATS;
    const float SC = 1.0f / 512.0f;
#pragma unroll
    for (int mf = 0; mf < 4; mf++)
#pragma unroll
        for (int nf = 0; nf < 4; nf++) {
            const float* c = acc[mf][nf];
            float2 f0 = __half22float2(*reinterpret_cast<const __half2*>(&accC[mf][nf][0]));
            float2 f1 = __half22float2(*reinterpret_cast<const __half2*>(&accC[mf][nf][1]));
            size_t r0 = row0 + wm + mf * 16 + g;
            size_t cc = col0 + wn + nf * 8 + 2 * t;
            *(float2*)(outb + r0 * DIMN + cc) =
                make_float2(c[0] + f0.x * SC, c[1] + f0.y * SC);
            *(float2*)(outb + (r0 + 8) * DIMN + cc) =
                make_float2(c[2] + f1.x * SC, c[3] + f1.y * SC);
        }
}

// ---------------- elementwise ----------------
__global__ __launch_bounds__(256)
void split_kernel(const float* __restrict__ in, __nv_bfloat16* __restrict__ h,
                  __nv_bfloat16* __restrict__ l)
{
    size_t i = (size_t)blockIdx.x * 256 + threadIdx.x;
    float4 v = ((const float4*)in)[i];
    union { __nv_bfloat16 b[4]; uint2 u; } H, L;
    bsplit(v.x, H.b[0], L.b[0]); bsplit(v.y, H.b[1], L.b[1]);
    bsplit(v.z, H.b[2], L.b[2]); bsplit(v.w, H.b[3], L.b[3]);
    ((uint2*)h)[i] = H.u;
    ((uint2*)l)[i] = L.u;
}

// fused: row-major bf16 split AND transposed fp16 split (lo*512) in one read
__global__ __launch_bounds__(256)
void fsplit_kernel(const float* __restrict__ in,
                   __nv_bfloat16* __restrict__ h,  __nv_bfloat16* __restrict__ l,
                   __half* __restrict__ th, __half* __restrict__ tl_)
{
    __shared__ float tle[32][33];
    const int z = blockIdx.z;
    const float* src = in + (size_t)z * MATS;
    const int bx = blockIdx.x * 32, by = blockIdx.y * 32;
    const int x = threadIdx.x, y = threadIdx.y;   // block (32, 8)
#pragma unroll
    for (int i = 0; i < 4; i++) {
        int row = by + y + 8 * i;
        float v = src[(size_t)row * DIMN + bx + x];
        tle[y + 8 * i][x] = v;
        __nv_bfloat16 hh, ll;
        bsplit(v, hh, ll);
        size_t o = (size_t)z * MATS + (size_t)row * DIMN + bx + x;
        h[o] = hh; l[o] = ll;
    }
    __syncthreads();
#pragma unroll
    for (int i = 0; i < 4; i++) {
        int cI = bx + y + 8 * i;
        float v = tle[x][y + 8 * i];
        __half hh, ll;
        hsplit(v, hh, ll);
        size_t o = (size_t)z * MATS + (size_t)cI * DIMN + by + x;
        th[o] = hh; tl_[o] = ll;
    }
}

// combine 8 (max,sum) partials -> (max, 1/sum)
__global__ __launch_bounds__(256)
void combine_kernel(const float* __restrict__ pm, const float* __restrict__ ps,
                    float* __restrict__ omax, float* __restrict__ oinv)
{
    int idx = blockIdx.x * 256 + threadIdx.x;
    const float* m8 = pm + (size_t)idx * 8;
    const float* s8 = ps + (size_t)idx * 8;
    float m = -1e30f;
#pragma unroll
    for (int j = 0; j < 8; j++) m = fmaxf(m, m8[j]);
    float s = 0.f;
#pragma unroll
    for (int j = 0; j < 8; j++) s += s8[j] * __expf(m8[j] - m);
    omax[idx] = m;
    oinv[idx] = 1.0f / s;
}

// fused: A1 = rowsoftmax(S) fp16 split AND A2T = colsoftmax(S)^T fp16 split
__global__ __launch_bounds__(256)
void softmax_apply(const float* __restrict__ S,
                   const float* __restrict__ rmax, const float* __restrict__ rinv,
                   const float* __restrict__ cmax, const float* __restrict__ cinv,
                   __half* __restrict__ A1h, __half* __restrict__ A1l,
                   __half* __restrict__ A2h, __half* __restrict__ A2l)
{
    __shared__ float tle[32][33];
    const int z = blockIdx.z;
    const int bx = blockIdx.x * 32, by = blockIdx.y * 32;
    const int x = threadIdx.x, y = threadIdx.y;
    const float* Sp = S + (size_t)z * MATS;
#pragma unroll
    for (int i = 0; i < 4; i++) {
        int row = by + y + 8 * i;
        float v = Sp[(size_t)row * DIMN + bx + x];
        tle[y + 8 * i][x] = v;
        float val = __expf(v - rmax[z * DIMN + row]) * rinv[z * DIMN + row];
        __half hh, ll;
        hsplit(val, hh, ll);
        size_t o = (size_t)z * MATS + (size_t)row * DIMN + bx + x;
        A1h[o] = hh; A1l[o] = ll;
    }
    __syncthreads();
#pragma unroll
    for (int i = 0; i < 4; i++) {
        int cI = bx + y + 8 * i;
        float v = tle[x][y + 8 * i];
        float val = __expf(v - cmax[z * DIMN + cI]) * cinv[z * DIMN + cI];
        __half hh, ll;
        hsplit(val, hh, ll);
        size_t o = (size_t)z * MATS + (size_t)cI * DIMN + by + x;
        A2h[o] = hh; A2l[o] = ll;
    }
}

// ---------------- capture-DAG helpers (no streams, no events) ----------------
static inline cudaGraphNode_t cap_tail() {
    cudaStreamCaptureStatus st = cudaStreamCaptureStatusNone;
    unsigned long long id = 0;
    cudaGraph_t gr = nullptr;
    const cudaGraphNode_t* deps = nullptr;
    const cudaGraphEdgeData* edges = nullptr;
    size_t nd = 0;
    cudaError_t e = cudaStreamGetCaptureInfo((cudaStream_t)0, &st, &id, &gr,
                                             &deps, &edges, &nd);
    if (e != cudaSuccess || st != cudaStreamCaptureStatusActive || nd < 1) {
        (void)cudaGetLastError();
        return nullptr;
    }
    return deps[nd - 1];
}
static inline void cap_set_deps(cudaGraphNode_t* nodes, size_t n) {
    if (!nodes || !nodes[0]) { (void)cudaGetLastError(); return; }
    (void)cudaStreamUpdateCaptureDependencies((cudaStream_t)0, nodes,
                                              (const cudaGraphEdgeData*)nullptr, n,
                                              cudaStreamSetCaptureDependencies);
    (void)cudaGetLastError();
}

// ---------------- launcher: fork-join DAG on one captured stream ----------------
extern "C" void kernel_launch(void* const* d_in, const int* in_sizes, int n_in,
                              void* d_out, int out_size)
{
    const float* a1 = (const float*)d_in[0];
    const float* a2 = (const float*)d_in[1];
    const float* Gw = (const float*)d_in[2];
    const float* Gb = (const float*)d_in[3];
    float* M1 = (float*)d_out;
    float* M2 = M1 + TOT;

    __nv_bfloat16 *a1h, *a1l, *a2h, *a2l, *gwh, *gwl, *a2ph, *a2pl;
    __half *A1h, *A1l, *A2h, *A2l, *a2Th, *a2Tl, *a1Th, *a1Tl;
    float *S, *rmax, *rinv, *cmax, *cinv, *rpm, *rps, *cpm, *cps;
    cudaGetSymbolAddress((void**)&a1h, g_a1h);   cudaGetSymbolAddress((void**)&a1l, g_a1l);
    cudaGetSymbolAddress((void**)&a2h, g_a2h);   cudaGetSymbolAddress((void**)&a2l, g_a2l);
    cudaGetSymbolAddress((void**)&gwh, g_gwh);   cudaGetSymbolAddress((void**)&gwl, g_gwl);
    cudaGetSymbolAddress((void**)&a2ph, g_a2ph); cudaGetSymbolAddress((void**)&a2pl, g_a2pl);
    cudaGetSymbolAddress((void**)&A1h, g_A1h);   cudaGetSymbolAddress((void**)&A1l, g_A1l);
    cudaGetSymbolAddress((void**)&A2h, g_A2h);   cudaGetSymbolAddress((void**)&A2l, g_A2l);
    cudaGetSymbolAddress((void**)&a2Th, g_a2Th); cudaGetSymbolAddress((void**)&a2Tl, g_a2Tl);
    cudaGetSymbolAddress((void**)&a1Th, g_a1Th); cudaGetSymbolAddress((void**)&a1Tl, g_a1Tl);
    cudaGetSymbolAddress((void**)&S, g_S);
    cudaGetSymbolAddress((void**)&rmax, g_rmax); cudaGetSymbolAddress((void**)&rinv, g_rinv);
    cudaGetSymbolAddress((void**)&cmax, g_cmax); cudaGetSymbolAddress((void**)&cinv, g_cinv);
    cudaGetSymbolAddress((void**)&rpm, g_rpm);   cudaGetSymbolAddress((void**)&rps, g_rps);
    cudaGetSymbolAddress((void**)&cpm, g_cpm);   cudaGetSymbolAddress((void**)&cps, g_cps);

    cudaFuncSetAttribute(gemm_a2p,  cudaFuncAttributeMaxDynamicSharedMemorySize, SMEM_TOT);
    cudaFuncSetAttribute(gemm_S,    cudaFuncAttributeMaxDynamicSharedMemorySize, SMEM_TOT);
    cudaFuncSetAttribute(gemm_dual, cudaFuncAttributeMaxDynamicSharedMemorySize, SMEM_TOT);

    // root: Gw split (cheap; fork point for all 4 groups)
    split_kernel<<<1024, 256>>>(Gw, gwh, gwl);
    cudaGraphNode_t nGw = cap_tail();

    cudaGraphNode_t nDual[4] = {};
    for (int grp = 0; grp < 4; grp++) {
        const size_t mo = (size_t)grp * 4 * MATS;      // matrix offset (4 batches)
        const size_t vo = (size_t)grp * 4 * DIMN;      // vector offset
        const size_t po = vo * 8;                       // partials offset

        // fork: both fsplits depend only on the Gw-split node
        cap_set_deps(&nGw, 1);
        fsplit_kernel<<<dim3(32, 32, 4), dim3(32, 8)>>>(
            a2 + mo, a2h + mo, a2l + mo, a2Th + mo, a2Tl + mo);
        cudaGraphNode_t nF2 = cap_tail();

        cap_set_deps(&nGw, 1);
        fsplit_kernel<<<dim3(32, 32, 4), dim3(32, 8)>>>(
            a1 + mo, a1h + mo, a1l + mo, a1Th + mo, a1Tl + mo);
        cudaGraphNode_t nF1 = cap_tail();

        // a2p depends on fsplit(a2) (+ Gw transitively)
        cap_set_deps(&nF2, 1);
        gemm_a2p<<<dim3(8, 32, 1), 256, SMEM_TOT>>>(
            a2h + mo, a2l + mo, gwh, gwl, a2ph + mo, a2pl + mo, Gb);
        cudaGraphNode_t nA2p = cap_tail();

        // S depends on fsplit(a1) + a2p
        {
            cudaGraphNode_t d2[2] = { nF1, nA2p };
            cap_set_deps(d2, (nF1 && nA2p) ? 2 : 1);
        }
        gemm_S<<<dim3(8, 8, 4), 256, SMEM_TOT>>>(
            a1h + mo, a1l + mo, a2ph + mo, a2pl + mo, S + mo,
            rpm + po, rps + po, cpm + po, cps + po);
        cudaGraphNode_t nS = cap_tail();

        // combines: both depend on S only (parallel)
        combine_kernel<<<16, 256>>>(rpm + po, rps + po, rmax + vo, rinv + vo);
        cudaGraphNode_t nCR = cap_tail();
        cap_set_deps(&nS, 1);
        combine_kernel<<<16, 256>>>(cpm + po, cps + po, cmax + vo, cinv + vo);
        cudaGraphNode_t nCC = cap_tail();

        // softmax apply depends on both combines
        {
            cudaGraphNode_t d2[2] = { nCR, nCC };
            cap_set_deps(d2, (nCR && nCC) ? 2 : 1);
        }
        softmax_apply<<<dim3(32, 32, 4), dim3(32, 8)>>>(
            S + mo, rmax + vo, rinv + vo, cmax + vo, cinv + vo,
            A1h + mo, A1l + mo, A2h + mo, A2l + mo);

        // dual GEMM (depends on softmax = current tail)
        gemm_dual<<<dim3(8, 8, 8), 256, SMEM_TOT>>>(
            A1h + mo, A1l + mo, a2Th + mo, a2Tl + mo, M1 + mo,
            A2h + mo, A2l + mo, a1Th + mo, a1Tl + mo, M2 + mo);
        nDual[grp] = cap_tail();
    }

    // join: subsequent captured work depends on all four group tails
    if (nDual[0] && nDual[1] && nDual[2] && nDual[3])
        cap_set_deps(nDual, 4);
}

// round 14
// speedup vs baseline: 1.0489x; 1.0489x over previous
#include <cuda_runtime.h>
#include <cuda_bf16.h>

#define DIMN 1024
#define NB 16
#define MATS ((size_t)DIMN * DIMN)     /* 1M  */
#define TOT  ((size_t)NB * MATS)       /* 16M */

// ---------------- scratch (device globals; allocation-free) ----------------
__device__ __nv_bfloat16 g_a1h[TOT],  g_a1l[TOT];
__device__ __nv_bfloat16 g_a2h[TOT],  g_a2l[TOT];
__device__ __nv_bfloat16 g_gwh[MATS], g_gwl[MATS];
__device__ __nv_bfloat16 g_a2ph[TOT], g_a2pl[TOT];
__device__ float         g_S[TOT];
__device__ __nv_bfloat16 g_A1h[TOT],  g_A1l[TOT];     // rowsoftmax(S)
__device__ __nv_bfloat16 g_A2h[TOT],  g_A2l[TOT];     // colsoftmax(S)^T
__device__ __nv_bfloat16 g_a2Th[TOT], g_a2Tl[TOT];    // a2^T
__device__ __nv_bfloat16 g_a1Th[TOT], g_a1Tl[TOT];    // a1^T
__device__ float g_rmax[NB * DIMN], g_rinv[NB * DIMN];
__device__ float g_cmax[NB * DIMN], g_cinv[NB * DIMN];
__device__ float g_rpm[NB * 8 * DIMN], g_rps[NB * 8 * DIMN];
__device__ float g_cpm[NB * 8 * DIMN], g_cps[NB * 8 * DIMN];

// ---------------- helpers ----------------
__device__ __forceinline__ unsigned smem_u32(const void* p) {
    unsigned r;
    asm("{ .reg .u64 t; cvta.to.shared.u64 t, %1; cvt.u32.u64 %0, t; }"
        : "=r"(r) : "l"(p));
    return r;
}
__device__ __forceinline__ unsigned swz64(unsigned x) { return x ^ ((x >> 3) & 0x30); }

__device__ __forceinline__ void bsplit(float v, __nv_bfloat16& h, __nv_bfloat16& l) {
    h = __float2bfloat16_rn(v);
    l = __float2bfloat16_rn(v - __bfloat162float(h));
}

#define CP16(dst, src) \
    asm volatile("cp.async.cg.shared.global [%0], [%1], 16;" :: "r"(dst), "l"(src))

#define LDSM4(r, addr) \
    asm volatile("ldmatrix.sync.aligned.m8n8.x4.shared.b16 {%0,%1,%2,%3}, [%4];" \
        : "=r"((r)[0]), "=r"((r)[1]), "=r"((r)[2]), "=r"((r)[3]) : "r"(addr))

#define MMA16816(c, a, b)                                                      \
    asm volatile("mma.sync.aligned.m16n8k16.row.col.f32.bf16.bf16.f32 "        \
        "{%0,%1,%2,%3}, {%4,%5,%6,%7}, {%8,%9}, {%0,%1,%2,%3};"                \
        : "+f"((c)[0]), "+f"((c)[1]), "+f"((c)[2]), "+f"((c)[3])               \
        : "r"((a)[0]), "r"((a)[1]), "r"((a)[2]), "r"((a)[3]),                  \
          "r"((b)[0]), "r"((b)[1]))

// ================= bf16 3-term NT GEMM core (R5-proven) ====================
// CTA 128x128, BK=32, 3-stage, 256 thr, 8 warps (2x4), warp 64x32.
#define STAGE_B   32768
#define SMEM_TOT  (3 * STAGE_B)

struct GPtr { const char *ah, *al, *bh, *bl; };

__device__ __forceinline__ void issue_loads_s(unsigned st, const GPtr& p, unsigned kbyte,
                                              unsigned so0, unsigned so1) {
    const unsigned RS = 64u * DIMN * 2u;
    CP16(st +     0 + so0, p.ah + kbyte);
    CP16(st +     0 + so1, p.ah + kbyte + RS);
    CP16(st +  8192 + so0, p.al + kbyte);
    CP16(st +  8192 + so1, p.al + kbyte + RS);
    CP16(st + 16384 + so0, p.bh + kbyte);
    CP16(st + 16384 + so1, p.bh + kbyte + RS);
    CP16(st + 24576 + so0, p.bl + kbyte);
    CP16(st + 24576 + so1, p.bl + kbyte + RS);
    asm volatile("cp.async.commit_group;" ::: "memory");
}

__device__ __forceinline__ void mainloop_s(unsigned sb, const GPtr& p,
                                           unsigned so0, unsigned so1,
                                           int lane, int wm, int wn,
                                           float (*acc)[4][4])
{
    issue_loads_s(sb,           p, 0,  so0, so1);
    issue_loads_s(sb + STAGE_B, p, 64, so0, so1);

#pragma unroll 1
    for (int it = 0; it < 32; it++) {
        if (it < 31) asm volatile("cp.async.wait_group 1;" ::: "memory");
        else         asm volatile("cp.async.wait_group 0;" ::: "memory");
        __syncthreads();
        if (it + 2 < 32) {
            unsigned wst = sb + (unsigned)((it + 2) % 3) * STAGE_B;
            issue_loads_s(wst, p, (unsigned)(it + 2) * 64, so0, so1);
        }
        const unsigned st = sb + (unsigned)(it % 3) * STAGE_B;

#pragma unroll
        for (int ks = 0; ks < 2; ks++) {
            const unsigned kb = ks * 32;
            unsigned bh[8], bl[8];
#pragma unroll
            for (int nt = 0; nt < 2; nt++) {
                unsigned brow = wn + nt * 16 + (lane & 7) + ((lane >> 4) & 1) * 8;
                unsigned bb   = kb + ((lane >> 3) & 1) * 16;
                unsigned ba   = st + 16384 + swz64(brow * 64 + bb);
                LDSM4(bh + nt * 4, ba);
                LDSM4(bl + nt * 4, ba + 8192);
            }
#pragma unroll
            for (int mf = 0; mf < 4; mf++) {
                unsigned arow = wm + mf * 16 + (lane & 15);
                unsigned ab   = kb + ((lane >> 4) & 1) * 16;
                unsigned aa   = st + swz64(arow * 64 + ab);
                unsigned ah[4], al[4];
                LDSM4(ah, aa);
                LDSM4(al, aa + 8192);
#pragma unroll
                for (int nf = 0; nf < 4; nf++) {
                    MMA16816(acc[mf][nf], ah, bh + nf * 2);
                    MMA16816(acc[mf][nf], ah, bl + nf * 2);
                    MMA16816(acc[mf][nf], al, bh + nf * 2);
                }
            }
        }
    }
}

__device__ __forceinline__ void make_gptr(GPtr& p, unsigned& so0, unsigned& so1,
    const __nv_bfloat16* Ah, const __nv_bfloat16* Al,
    const __nv_bfloat16* Bh, const __nv_bfloat16* Bl,
    size_t zA, size_t zB, size_t row0, size_t col0, int tid)
{
    size_t ar = row0 + (tid >> 2);
    size_t br = col0 + (tid >> 2);
    size_t ko = (size_t)(tid & 3) * 8;
    p.ah = (const char*)Ah + (zA + ar * DIMN + ko) * 2;
    p.al = (const char*)Al + (zA + ar * DIMN + ko) * 2;
    p.bh = (const char*)Bh + (zB + br * DIMN + ko) * 2;
    p.bl = (const char*)Bl + (zB + br * DIMN + ko) * 2;
    so0 = swz64(((unsigned)(tid >> 2)) * 64 + (tid & 3) * 16);
    so1 = so0 + 4096;
}

// ---- a2p GEMM: bias add + split bf16 pair out ----
__global__ __launch_bounds__(256, 2)
void gemm_a2p(const __nv_bfloat16* __restrict__ Ah, const __nv_bfloat16* __restrict__ Al,
              const __nv_bfloat16* __restrict__ Bh, const __nv_bfloat16* __restrict__ Bl,
              __nv_bfloat16* __restrict__ outH, __nv_bfloat16* __restrict__ outL,
              const float* __restrict__ bias)
{
    extern __shared__ char smem[];
    const unsigned sb = smem_u32(smem);
    const int tid = threadIdx.x, warp = tid >> 5, lane = tid & 31;
    const int wm = (warp >> 2) * 64, wn = (warp & 3) * 32;
    const size_t row0 = (size_t)blockIdx.y * 128, col0 = (size_t)blockIdx.x * 128;

    GPtr p; unsigned so0, so1;
    make_gptr(p, so0, so1, Ah, Al, Bh, Bl, 0, 0, row0, col0, tid);
    float acc[4][4][4] = {};
    mainloop_s(sb, p, so0, so1, lane, wm, wn, acc);

    const int g = lane >> 2, t = lane & 3;
#pragma unroll
    for (int mf = 0; mf < 4; mf++)
#pragma unroll
        for (int nf = 0; nf < 4; nf++) {
            const float* c = acc[mf][nf];
            size_t r0 = row0 + wm + mf * 16 + g;
            size_t cc = col0 + wn + nf * 8 + 2 * t;
            float b0 = bias[cc], b1 = bias[cc + 1];
            union { __nv_bfloat16 b[2]; unsigned u; } H0, L0, H1, L1;
            bsplit(c[0] + b0, H0.b[0], L0.b[0]);
            bsplit(c[1] + b1, H0.b[1], L0.b[1]);
            bsplit(c[2] + b0, H1.b[0], L1.b[0]);
            bsplit(c[3] + b1, H1.b[1], L1.b[1]);
            *(unsigned*)(outH + r0 * DIMN + cc)       = H0.u;
            *(unsigned*)(outL + r0 * DIMN + cc)       = L0.u;
            *(unsigned*)(outH + (r0 + 8) * DIMN + cc) = H1.u;
            *(unsigned*)(outL + (r0 + 8) * DIMN + cc) = L1.u;
        }
}

// ---- S GEMM: fp32 out + fused per-CTA row/col softmax partials ----
__global__ __launch_bounds__(256, 2)
void gemm_S(const __nv_bfloat16* __restrict__ Ah, const __nv_bfloat16* __restrict__ Al,
            const __nv_bfloat16* __restrict__ Bh, const __nv_bfloat16* __restrict__ Bl,
            float* __restrict__ outF,
            float* __restrict__ rpm, float* __restrict__ rps,
            float* __restrict__ cpm, float* __restrict__ cps)
{
    extern __shared__ char smem[];
    const unsigned sb = smem_u32(smem);
    const int tid = threadIdx.x, warp = tid >> 5, lane = tid & 31;
    const int wm = (warp >> 2) * 64, wn = (warp & 3) * 32;
    const size_t z = blockIdx.z;
    const size_t row0 = (size_t)blockIdx.y * 128, col0 = (size_t)blockIdx.x * 128;

    GPtr p; unsigned so0, so1;
    make_gptr(p, so0, so1, Ah, Al, Bh, Bl, z * MATS, z * MATS, row0, col0, tid);
    float acc[4][4][4] = {};
    mainloop_s(sb, p, so0, so1, lane, wm, wn, acc);

    const int g = lane >> 2, t = lane & 3;
    float* outb = outF + z * MATS;
#pragma unroll
    for (int mf = 0; mf < 4; mf++)
#pragma unroll
        for (int nf = 0; nf < 4; nf++) {
            const float* c = acc[mf][nf];
            size_t r0 = row0 + wm + mf * 16 + g;
            size_t cc = col0 + wn + nf * 8 + 2 * t;
            *(float2*)(outb + r0 * DIMN + cc)       = make_float2(c[0], c[1]);
            *(float2*)(outb + (r0 + 8) * DIMN + cc) = make_float2(c[2], c[3]);
        }

    // ---- softmax partials from registers ----
    float rm_[4][2], rs_[4][2];
#pragma unroll
    for (int mf = 0; mf < 4; mf++)
#pragma unroll
        for (int rh = 0; rh < 2; rh++) {
            float m = -1e30f;
#pragma unroll
            for (int nf = 0; nf < 4; nf++)
                m = fmaxf(m, fmaxf(acc[mf][nf][rh * 2], acc[mf][nf][rh * 2 + 1]));
            m = fmaxf(m, __shfl_xor_sync(0xffffffffu, m, 1));
            m = fmaxf(m, __shfl_xor_sync(0xffffffffu, m, 2));
            float s = 0.f;
#pragma unroll
            for (int nf = 0; nf < 4; nf++)
                s += __expf(acc[mf][nf][rh * 2] - m) + __expf(acc[mf][nf][rh * 2 + 1] - m);
            s += __shfl_xor_sync(0xffffffffu, s, 1);
            s += __shfl_xor_sync(0xffffffffu, s, 2);
            rm_[mf][rh] = m; rs_[mf][rh] = s;
        }
    float cm_[4][2], cs_[4][2];
#pragma unroll
    for (int nf = 0; nf < 4; nf++)
#pragma unroll
        for (int cr = 0; cr < 2; cr++) {
            float m = -1e30f;
#pragma unroll
            for (int mf = 0; mf < 4; mf++)
                m = fmaxf(m, fmaxf(acc[mf][nf][cr], acc[mf][nf][2 + cr]));
            m = fmaxf(m, __shfl_xor_sync(0xffffffffu, m, 4));
            m = fmaxf(m, __shfl_xor_sync(0xffffffffu, m, 8));
            m = fmaxf(m, __shfl_xor_sync(0xffffffffu, m, 16));
            float s = 0.f;
#pragma unroll
            for (int mf = 0; mf < 4; mf++)
                s += __expf(acc[mf][nf][cr] - m) + __expf(acc[mf][nf][2 + cr] - m);
            s += __shfl_xor_sync(0xffffffffu, s, 4);
            s += __shfl_xor_sync(0xffffffffu, s, 8);
            s += __shfl_xor_sync(0xffffffffu, s, 16);
            cm_[nf][cr] = m; cs_[nf][cr] = s;
        }

    __syncthreads();   // stage buffers dead; reuse smem for staging
    float* sRM = (float*)smem;        // [4][128]
    float* sRS = sRM + 512;
    float* sCM = sRS + 512;           // [2][128]
    float* sCS = sCM + 256;
    if (t == 0) {
#pragma unroll
        for (int mf = 0; mf < 4; mf++)
#pragma unroll
            for (int rh = 0; rh < 2; rh++) {
                int r = wm + mf * 16 + g + 8 * rh;
                sRM[(warp & 3) * 128 + r] = rm_[mf][rh];
                sRS[(warp & 3) * 128 + r] = rs_[mf][rh];
            }
    }
    if (g == 0) {
#pragma unroll
        for (int nf = 0; nf < 4; nf++)
#pragma unroll
            for (int cr = 0; cr < 2; cr++) {
                int c = wn + nf * 8 + 2 * t + cr;
                sCM[(warp >> 2) * 128 + c] = cm_[nf][cr];
                sCS[(warp >> 2) * 128 + c] = cs_[nf][cr];
            }
    }
    __syncthreads();
    if (tid < 128) {
        int r = tid;
        float m = -1e30f;
#pragma unroll
        for (int w = 0; w < 4; w++) m = fmaxf(m, sRM[w * 128 + r]);
        float s = 0.f;
#pragma unroll
        for (int w = 0; w < 4; w++) s += sRS[w * 128 + r] * __expf(sRM[w * 128 + r] - m);
        size_t ri = (z * DIMN + row0 + r) * 8 + blockIdx.x;
        rpm[ri] = m; rps[ri] = s;

        int c = tid;
        float mc = fmaxf(sCM[c], sCM[128 + c]);
        float sc = sCS[c] * __expf(sCM[c] - mc) + sCS[128 + c] * __expf(sCM[128 + c] - mc);
        size_t ci = (z * DIMN + col0 + c) * 8 + blockIdx.y;
        cpm[ci] = mc; cps[ci] = sc;
    }
}

// ---- merged M1/M2 GEMM per chain of 2 batches: grid z in [0,4), sel = z>>1 ----
__global__ __launch_bounds__(256, 2)
void gemm_dual(const __nv_bfloat16* __restrict__ A1h, const __nv_bfloat16* __restrict__ A1l,
               const __nv_bfloat16* __restrict__ B1h, const __nv_bfloat16* __restrict__ B1l,
               float* __restrict__ o1,
               const __nv_bfloat16* __restrict__ A2h, const __nv_bfloat16* __restrict__ A2l,
               const __nv_bfloat16* __restrict__ B2h, const __nv_bfloat16* __restrict__ B2l,
               float* __restrict__ o2)
{
    extern __shared__ char smem[];
    const unsigned sb = smem_u32(smem);
    const int tid = threadIdx.x, warp = tid >> 5, lane = tid & 31;
    const int wm = (warp >> 2) * 64, wn = (warp & 3) * 32;
    const int sel = blockIdx.z >> 1;
    const size_t z = blockIdx.z & 1;
    const size_t row0 = (size_t)blockIdx.y * 128, col0 = (size_t)blockIdx.x * 128;

    const __nv_bfloat16* Ah = sel ? A2h : A1h;
    const __nv_bfloat16* Al = sel ? A2l : A1l;
    const __nv_bfloat16* Bh = sel ? B2h : B1h;
    const __nv_bfloat16* Bl = sel ? B2l : B1l;
    float* outF = sel ? o2 : o1;

    GPtr p; unsigned so0, so1;
    make_gptr(p, so0, so1, Ah, Al, Bh, Bl, z * MATS, z * MATS, row0, col0, tid);
    float acc[4][4][4] = {};
    mainloop_s(sb, p, so0, so1, lane, wm, wn, acc);

    const int g = lane >> 2, t = lane & 3;
    float* outb = outF + z * MATS;
#pragma unroll
    for (int mf = 0; mf < 4; mf++)
#pragma unroll
        for (int nf = 0; nf < 4; nf++) {
            const float* c = acc[mf][nf];
            size_t r0 = row0 + wm + mf * 16 + g;
            size_t cc = col0 + wn + nf * 8 + 2 * t;
            *(float2*)(outb + r0 * DIMN + cc)       = make_float2(c[0], c[1]);
            *(float2*)(outb + (r0 + 8) * DIMN + cc) = make_float2(c[2], c[3]);
        }
}

// ---------------- elementwise ----------------
__global__ __launch_bounds__(256)
void split_kernel(const float* __restrict__ in, __nv_bfloat16* __restrict__ h,
                  __nv_bfloat16* __restrict__ l)
{
    size_t i = (size_t)blockIdx.x * 256 + threadIdx.x;
    float4 v = ((const float4*)in)[i];
    union { __nv_bfloat16 b[4]; uint2 u; } H, L;
    bsplit(v.x, H.b[0], L.b[0]); bsplit(v.y, H.b[1], L.b[1]);
    bsplit(v.z, H.b[2], L.b[2]); bsplit(v.w, H.b[3], L.b[3]);
    ((uint2*)h)[i] = H.u;
    ((uint2*)l)[i] = L.u;
}

// fused: row-major split AND transposed split in one read of the input
__global__ __launch_bounds__(256)
void fsplit_kernel(const float* __restrict__ in,
                   __nv_bfloat16* __restrict__ h,  __nv_bfloat16* __restrict__ l,
                   __nv_bfloat16* __restrict__ th, __nv_bfloat16* __restrict__ tl_)
{
    __shared__ float tle[32][33];
    const int z = blockIdx.z;
    const float* src = in + (size_t)z * MATS;
    const int bx = blockIdx.x * 32, by = blockIdx.y * 32;
    const int x = threadIdx.x, y = threadIdx.y;   // block (32, 8)
#pragma unroll
    for (int i = 0; i < 4; i++) {
        int row = by + y + 8 * i;
        float v = src[(size_t)row * DIMN + bx + x];
        tle[y + 8 * i][x] = v;
        __nv_bfloat16 hh, ll;
        bsplit(v, hh, ll);
        size_t o = (size_t)z * MATS + (size_t)row * DIMN + bx + x;
        h[o] = hh; l[o] = ll;
    }
    __syncthreads();
#pragma unroll
    for (int i = 0; i < 4; i++) {
        int cI = bx + y + 8 * i;
        float v = tle[x][y + 8 * i];
        __nv_bfloat16 hh, ll;
        bsplit(v, hh, ll);
        size_t o = (size_t)z * MATS + (size_t)cI * DIMN + by + x;
        th[o] = hh; tl_[o] = ll;
    }
}

// combine 8 (max,sum) partials -> (max, 1/sum)
__global__ __launch_bounds__(256)
void combine_kernel(const float* __restrict__ pm, const float* __restrict__ ps,
                    float* __restrict__ omax, float* __restrict__ oinv)
{
    int idx = blockIdx.x * 256 + threadIdx.x;
    const float* m8 = pm + (size_t)idx * 8;
    const float* s8 = ps + (size_t)idx * 8;
    float m = -1e30f;
#pragma unroll
    for (int j = 0; j < 8; j++) m = fmaxf(m, m8[j]);
    float s = 0.f;
#pragma unroll
    for (int j = 0; j < 8; j++) s += s8[j] * __expf(m8[j] - m);
    omax[idx] = m;
    oinv[idx] = 1.0f / s;
}

// fused: A1 = rowsoftmax(S) split (row-major) AND A2T = colsoftmax(S)^T split
__global__ __launch_bounds__(256)
void softmax_apply(const float* __restrict__ S,
                   const float* __restrict__ rmax, const float* __restrict__ rinv,
                   const float* __restrict__ cmax, const float* __restrict__ cinv,
                   __nv_bfloat16* __restrict__ A1h, __nv_bfloat16* __restrict__ A1l,
                   __nv_bfloat16* __restrict__ A2h, __nv_bfloat16* __restrict__ A2l)
{
    __shared__ float tle[32][33];
    const int z = blockIdx.z;
    const int bx = blockIdx.x * 32, by = blockIdx.y * 32;
    const int x = threadIdx.x, y = threadIdx.y;
    const float* Sp = S + (size_t)z * MATS;
#pragma unroll
    for (int i = 0; i < 4; i++) {
        int row = by + y + 8 * i;
        float v = Sp[(size_t)row * DIMN + bx + x];
        tle[y + 8 * i][x] = v;
        float val = __expf(v - rmax[z * DIMN + row]) * rinv[z * DIMN + row];
        __nv_bfloat16 hh, ll;
        bsplit(val, hh, ll);
        size_t o = (size_t)z * MATS + (size_t)row * DIMN + bx + x;
        A1h[o] = hh; A1l[o] = ll;
    }
    __syncthreads();
#pragma unroll
    for (int i = 0; i < 4; i++) {
        int cI = bx + y + 8 * i;
        float v = tle[x][y + 8 * i];
        float val = __expf(v - cmax[z * DIMN + cI]) * cinv[z * DIMN + cI];
        __nv_bfloat16 hh, ll;
        bsplit(val, hh, ll);
        size_t o = (size_t)z * MATS + (size_t)cI * DIMN + by + x;
        A2h[o] = hh; A2l[o] = ll;
    }
}

// ---------------- capture-DAG helpers (no streams, no events) ----------------
static inline cudaGraphNode_t cap_tail() {
    cudaStreamCaptureStatus st = cudaStreamCaptureStatusNone;
    unsigned long long id = 0;
    cudaGraph_t gr = nullptr;
    const cudaGraphNode_t* deps = nullptr;
    const cudaGraphEdgeData* edges = nullptr;
    size_t nd = 0;
    cudaError_t e = cudaStreamGetCaptureInfo((cudaStream_t)0, &st, &id, &gr,
                                             &deps, &edges, &nd);
    if (e != cudaSuccess || st != cudaStreamCaptureStatusActive || nd < 1) {
        (void)cudaGetLastError();
        return nullptr;
    }
    return deps[nd - 1];
}
static inline void cap_set_deps(cudaGraphNode_t* nodes, size_t n) {
    if (!nodes || !nodes[0]) { (void)cudaGetLastError(); return; }
    (void)cudaStreamUpdateCaptureDependencies((cudaStream_t)0, nodes,
                                              (const cudaGraphEdgeData*)nullptr, n,
                                              cudaStreamSetCaptureDependencies);
    (void)cudaGetLastError();
}

// ---------------- launcher: 8-chain fork-join DAG on one captured stream ----
extern "C" void kernel_launch(void* const* d_in, const int* in_sizes, int n_in,
                              void* d_out, int out_size)
{
    const float* a1 = (const float*)d_in[0];
    const float* a2 = (const float*)d_in[1];
    const float* Gw = (const float*)d_in[2];
    const float* Gb = (const float*)d_in[3];
    float* M1 = (float*)d_out;
    float* M2 = M1 + TOT;

    __nv_bfloat16 *a1h, *a1l, *a2h, *a2l, *gwh, *gwl, *a2ph, *a2pl;
    __nv_bfloat16 *A1h, *A1l, *A2h, *A2l, *a2Th, *a2Tl, *a1Th, *a1Tl;
    float *S, *rmax, *rinv, *cmax, *cinv, *rpm, *rps, *cpm, *cps;
    cudaGetSymbolAddress((void**)&a1h, g_a1h);   cudaGetSymbolAddress((void**)&a1l, g_a1l);
    cudaGetSymbolAddress((void**)&a2h, g_a2h);   cudaGetSymbolAddress((void**)&a2l, g_a2l);
    cudaGetSymbolAddress((void**)&gwh, g_gwh);   cudaGetSymbolAddress((void**)&gwl, g_gwl);
    cudaGetSymbolAddress((void**)&a2ph, g_a2ph); cudaGetSymbolAddress((void**)&a2pl, g_a2pl);
    cudaGetSymbolAddress((void**)&A1h, g_A1h);   cudaGetSymbolAddress((void**)&A1l, g_A1l);
    cudaGetSymbolAddress((void**)&A2h, g_A2h);   cudaGetSymbolAddress((void**)&A2l, g_A2l);
    cudaGetSymbolAddress((void**)&a2Th, g_a2Th); cudaGetSymbolAddress((void**)&a2Tl, g_a2Tl);
    cudaGetSymbolAddress((void**)&a1Th, g_a1Th); cudaGetSymbolAddress((void**)&a1Tl, g_a1Tl);
    cudaGetSymbolAddress((void**)&S, g_S);
    cudaGetSymbolAddress((void**)&rmax, g_rmax); cudaGetSymbolAddress((void**)&rinv, g_rinv);
    cudaGetSymbolAddress((void**)&cmax, g_cmax); cudaGetSymbolAddress((void**)&cinv, g_cinv);
    cudaGetSymbolAddress((void**)&rpm, g_rpm);   cudaGetSymbolAddress((void**)&rps, g_rps);
    cudaGetSymbolAddress((void**)&cpm, g_cpm);   cudaGetSymbolAddress((void**)&cps, g_cps);

    cudaFuncSetAttribute(gemm_a2p,  cudaFuncAttributeMaxDynamicSharedMemorySize, SMEM_TOT);
    cudaFuncSetAttribute(gemm_S,    cudaFuncAttributeMaxDynamicSharedMemorySize, SMEM_TOT);
    cudaFuncSetAttribute(gemm_dual, cudaFuncAttributeMaxDynamicSharedMemorySize, SMEM_TOT);

    // root: Gw split (cheap; fork point for all chains)
    split_kernel<<<1024, 256>>>(Gw, gwh, gwl);
    cudaGraphNode_t nGw = cap_tail();

    cudaGraphNode_t nDual[8] = {};
    for (int grp = 0; grp < 8; grp++) {
        const size_t mo = (size_t)grp * 2 * MATS;      // matrix offset (2 batches)
        const size_t vo = (size_t)grp * 2 * DIMN;      // vector offset
        const size_t po = vo * 8;                       // partials offset

        // fork: both fsplits depend only on the Gw-split node
        cap_set_deps(&nGw, 1);
        fsplit_kernel<<<dim3(32, 32, 2), dim3(32, 8)>>>(
            a2 + mo, a2h + mo, a2l + mo, a2Th + mo, a2Tl + mo);
        cudaGraphNode_t nF2 = cap_tail();

        cap_set_deps(&nGw, 1);
        fsplit_kernel<<<dim3(32, 32, 2), dim3(32, 8)>>>(
            a1 + mo, a1h + mo, a1l + mo, a1Th + mo, a1Tl + mo);
        cudaGraphNode_t nF1 = cap_tail();

        // a2p depends on fsplit(a2) (+ Gw transitively)
        cap_set_deps(&nF2, 1);
        gemm_a2p<<<dim3(8, 16, 1), 256, SMEM_TOT>>>(
            a2h + mo, a2l + mo, gwh, gwl, a2ph + mo, a2pl + mo, Gb);
        cudaGraphNode_t nA2p = cap_tail();

        // S depends on fsplit(a1) + a2p
        {
            cudaGraphNode_t d2[2] = { nF1, nA2p };
            cap_set_deps(d2, (nF1 && nA2p) ? 2 : 1);
        }
        gemm_S<<<dim3(8, 8, 2), 256, SMEM_TOT>>>(
            a1h + mo, a1l + mo, a2ph + mo, a2pl + mo, S + mo,
            rpm + po, rps + po, cpm + po, cps + po);
        cudaGraphNode_t nS = cap_tail();

        // combines: both depend on S only (parallel)
        combine_kernel<<<8, 256>>>(rpm + po, rps + po, rmax + vo, rinv + vo);
        cudaGraphNode_t nCR = cap_tail();
        cap_set_deps(&nS, 1);
        combine_kernel<<<8, 256>>>(cpm + po, cps + po, cmax + vo, cinv + vo);
        cudaGraphNode_t nCC = cap_tail();

        // softmax apply depends on both combines
        {
            cudaGraphNode_t d2[2] = { nCR, nCC };
            cap_set_deps(d2, (nCR && nCC) ? 2 : 1);
        }
        softmax_apply<<<dim3(32, 32, 2), dim3(32, 8)>>>(
            S + mo, rmax + vo, rinv + vo, cmax + vo, cinv + vo,
            A1h + mo, A1l + mo, A2h + mo, A2l + mo);

        // dual GEMM (depends on softmax = current tail)
        gemm_dual<<<dim3(8, 8, 4), 256, SMEM_TOT>>>(
            A1h + mo, A1l + mo, a2Th + mo, a2Tl + mo, M1 + mo,
            A2h + mo, A2l + mo, a1Th + mo, a1Tl + mo, M2 + mo);
        nDual[grp] = cap_tail();
    }

    // join: subsequent captured work depends on all chain tails
    bool all = true;
    for (int i = 0; i < 8; i++) all = all && (nDual[i] != nullptr);
    if (all) cap_set_deps(nDual, 8);
}

// round 15
// speedup vs baseline: 1.0723x; 1.0223x over previous
#include <cuda_runtime.h>
#include <cuda_bf16.h>

#define DIMN 1024
#define NB 16
#define MATS ((size_t)DIMN * DIMN)     /* 1M  */
#define TOT  ((size_t)NB * MATS)       /* 16M */

// ---------------- scratch (device globals; allocation-free) ----------------
__device__ __nv_bfloat16 g_a1h[TOT],  g_a1l[TOT];
__device__ __nv_bfloat16 g_a2h[TOT],  g_a2l[TOT];
__device__ __nv_bfloat16 g_gwh[MATS], g_gwl[MATS];
__device__ __nv_bfloat16 g_a2ph[TOT], g_a2pl[TOT];
__device__ float         g_S[TOT];
__device__ __nv_bfloat16 g_A1h[TOT],  g_A1l[TOT];     // rowsoftmax(S)
__device__ __nv_bfloat16 g_A2h[TOT],  g_A2l[TOT];     // colsoftmax(S)^T
__device__ __nv_bfloat16 g_a2Th[TOT], g_a2Tl[TOT];    // a2^T
__device__ __nv_bfloat16 g_a1Th[TOT], g_a1Tl[TOT];    // a1^T
__device__ float g_rmax[NB * DIMN], g_rinv[NB * DIMN];
__device__ float g_cmax[NB * DIMN], g_cinv[NB * DIMN];
__device__ float g_rpm[NB * 8 * DIMN], g_rps[NB * 8 * DIMN];
__device__ float g_cpm[NB * 8 * DIMN], g_cps[NB * 8 * DIMN];

// ---------------- helpers ----------------
__device__ __forceinline__ unsigned smem_u32(const void* p) {
    unsigned r;
    asm("{ .reg .u64 t; cvta.to.shared.u64 t, %1; cvt.u32.u64 %0, t; }"
        : "=r"(r) : "l"(p));
    return r;
}
__device__ __forceinline__ unsigned swz64(unsigned x) { return x ^ ((x >> 3) & 0x30); }

__device__ __forceinline__ void bsplit(float v, __nv_bfloat16& h, __nv_bfloat16& l) {
    h = __float2bfloat16_rn(v);
    l = __float2bfloat16_rn(v - __bfloat162float(h));
}

#define CP16(dst, src) \
    asm volatile("cp.async.cg.shared.global [%0], [%1], 16;" :: "r"(dst), "l"(src))

#define LDSM4(r, addr) \
    asm volatile("ldmatrix.sync.aligned.m8n8.x4.shared.b16 {%0,%1,%2,%3}, [%4];" \
        : "=r"((r)[0]), "=r"((r)[1]), "=r"((r)[2]), "=r"((r)[3]) : "r"(addr))

#define MMA16816(c, a, b)                                                      \
    asm volatile("mma.sync.aligned.m16n8k16.row.col.f32.bf16.bf16.f32 "        \
        "{%0,%1,%2,%3}, {%4,%5,%6,%7}, {%8,%9}, {%0,%1,%2,%3};"                \
        : "+f"((c)[0]), "+f"((c)[1]), "+f"((c)[2]), "+f"((c)[3])               \
        : "r"((a)[0]), "r"((a)[1]), "r"((a)[2]), "r"((a)[3]),                  \
          "r"((b)[0]), "r"((b)[1]))

// ================= bf16 3-term NT GEMM core (R5-proven) ====================
// CTA 128x128, BK=32, 3-stage, 256 thr, 8 warps (2x4), warp 64x32.
#define STAGE_B   32768
#define SMEM_TOT  (3 * STAGE_B)

struct GPtr { const char *ah, *al, *bh, *bl; };

__device__ __forceinline__ void issue_loads_s(unsigned st, const GPtr& p, unsigned kbyte,
                                              unsigned so0, unsigned so1) {
    const unsigned RS = 64u * DIMN * 2u;
    CP16(st +     0 + so0, p.ah + kbyte);
    CP16(st +     0 + so1, p.ah + kbyte + RS);
    CP16(st +  8192 + so0, p.al + kbyte);
    CP16(st +  8192 + so1, p.al + kbyte + RS);
    CP16(st + 16384 + so0, p.bh + kbyte);
    CP16(st + 16384 + so1, p.bh + kbyte + RS);
    CP16(st + 24576 + so0, p.bl + kbyte);
    CP16(st + 24576 + so1, p.bl + kbyte + RS);
    asm volatile("cp.async.commit_group;" ::: "memory");
}

__device__ __forceinline__ void mainloop_s(unsigned sb, const GPtr& p,
                                           unsigned so0, unsigned so1,
                                           int lane, int wm, int wn,
                                           float (*acc)[4][4])
{
    issue_loads_s(sb,           p, 0,  so0, so1);
    issue_loads_s(sb + STAGE_B, p, 64, so0, so1);

#pragma unroll 1
    for (int it = 0; it < 32; it++) {
        if (it < 31) asm volatile("cp.async.wait_group 1;" ::: "memory");
        else         asm volatile("cp.async.wait_group 0;" ::: "memory");
        __syncthreads();
        if (it + 2 < 32) {
            unsigned wst = sb + (unsigned)((it + 2) % 3) * STAGE_B;
            issue_loads_s(wst, p, (unsigned)(it + 2) * 64, so0, so1);
        }
        const unsigned st = sb + (unsigned)(it % 3) * STAGE_B;

#pragma unroll
        for (int ks = 0; ks < 2; ks++) {
            const unsigned kb = ks * 32;
            unsigned bh[8], bl[8];
#pragma unroll
            for (int nt = 0; nt < 2; nt++) {
                unsigned brow = wn + nt * 16 + (lane & 7) + ((lane >> 4) & 1) * 8;
                unsigned bb   = kb + ((lane >> 3) & 1) * 16;
                unsigned ba   = st + 16384 + swz64(brow * 64 + bb);
                LDSM4(bh + nt * 4, ba);
                LDSM4(bl + nt * 4, ba + 8192);
            }
#pragma unroll
            for (int mf = 0; mf < 4; mf++) {
                unsigned arow = wm + mf * 16 + (lane & 15);
                unsigned ab   = kb + ((lane >> 4) & 1) * 16;
                unsigned aa   = st + swz64(arow * 64 + ab);
                unsigned ah[4], al[4];
                LDSM4(ah, aa);
                LDSM4(al, aa + 8192);
#pragma unroll
                for (int nf = 0; nf < 4; nf++) {
                    MMA16816(acc[mf][nf], ah, bh + nf * 2);
                    MMA16816(acc[mf][nf], ah, bl + nf * 2);
                    MMA16816(acc[mf][nf], al, bh + nf * 2);
                }
            }
        }
    }
}

__device__ __forceinline__ void make_gptr(GPtr& p, unsigned& so0, unsigned& so1,
    const __nv_bfloat16* Ah, const __nv_bfloat16* Al,
    const __nv_bfloat16* Bh, const __nv_bfloat16* Bl,
    size_t zA, size_t zB, size_t row0, size_t col0, int tid)
{
    size_t ar = row0 + (tid >> 2);
    size_t br = col0 + (tid >> 2);
    size_t ko = (size_t)(tid & 3) * 8;
    p.ah = (const char*)Ah + (zA + ar * DIMN + ko) * 2;
    p.al = (const char*)Al + (zA + ar * DIMN + ko) * 2;
    p.bh = (const char*)Bh + (zB + br * DIMN + ko) * 2;
    p.bl = (const char*)Bl + (zB + br * DIMN + ko) * 2;
    so0 = swz64(((unsigned)(tid >> 2)) * 64 + (tid & 3) * 16);
    so1 = so0 + 4096;
}

// ---- a2p GEMM: bias add + split bf16 pair out ----
__global__ __launch_bounds__(256, 2)
void gemm_a2p(const __nv_bfloat16* __restrict__ Ah, const __nv_bfloat16* __restrict__ Al,
              const __nv_bfloat16* __restrict__ Bh, const __nv_bfloat16* __restrict__ Bl,
              __nv_bfloat16* __restrict__ outH, __nv_bfloat16* __restrict__ outL,
              const float* __restrict__ bias)
{
    extern __shared__ char smem[];
    const unsigned sb = smem_u32(smem);
    const int tid = threadIdx.x, warp = tid >> 5, lane = tid & 31;
    const int wm = (warp >> 2) * 64, wn = (warp & 3) * 32;
    const size_t row0 = (size_t)blockIdx.y * 128, col0 = (size_t)blockIdx.x * 128;

    GPtr p; unsigned so0, so1;
    make_gptr(p, so0, so1, Ah, Al, Bh, Bl, 0, 0, row0, col0, tid);
    float acc[4][4][4] = {};
    mainloop_s(sb, p, so0, so1, lane, wm, wn, acc);

    const int g = lane >> 2, t = lane & 3;
#pragma unroll
    for (int mf = 0; mf < 4; mf++)
#pragma unroll
        for (int nf = 0; nf < 4; nf++) {
            const float* c = acc[mf][nf];
            size_t r0 = row0 + wm + mf * 16 + g;
            size_t cc = col0 + wn + nf * 8 + 2 * t;
            float b0 = bias[cc], b1 = bias[cc + 1];
            union { __nv_bfloat16 b[2]; unsigned u; } H0, L0, H1, L1;
            bsplit(c[0] + b0, H0.b[0], L0.b[0]);
            bsplit(c[1] + b1, H0.b[1], L0.b[1]);
            bsplit(c[2] + b0, H1.b[0], L1.b[0]);
            bsplit(c[3] + b1, H1.b[1], L1.b[1]);
            *(unsigned*)(outH + r0 * DIMN + cc)       = H0.u;
            *(unsigned*)(outL + r0 * DIMN + cc)       = L0.u;
            *(unsigned*)(outH + (r0 + 8) * DIMN + cc) = H1.u;
            *(unsigned*)(outL + (r0 + 8) * DIMN + cc) = L1.u;
        }
}

// ---- S GEMM: fp32 out + fused per-CTA row/col softmax partials ----
__global__ __launch_bounds__(256, 2)
void gemm_S(const __nv_bfloat16* __restrict__ Ah, const __nv_bfloat16* __restrict__ Al,
            const __nv_bfloat16* __restrict__ Bh, const __nv_bfloat16* __restrict__ Bl,
            float* __restrict__ outF,
            float* __restrict__ rpm, float* __restrict__ rps,
            float* __restrict__ cpm, float* __restrict__ cps)
{
    extern __shared__ char smem[];
    const unsigned sb = smem_u32(smem);
    const int tid = threadIdx.x, warp = tid >> 5, lane = tid & 31;
    const int wm = (warp >> 2) * 64, wn = (warp & 3) * 32;
    const size_t z = blockIdx.z;
    const size_t row0 = (size_t)blockIdx.y * 128, col0 = (size_t)blockIdx.x * 128;

    GPtr p; unsigned so0, so1;
    make_gptr(p, so0, so1, Ah, Al, Bh, Bl, z * MATS, z * MATS, row0, col0, tid);
    float acc[4][4][4] = {};
    mainloop_s(sb, p, so0, so1, lane, wm, wn, acc);

    const int g = lane >> 2, t = lane & 3;
    float* outb = outF + z * MATS;
#pragma unroll
    for (int mf = 0; mf < 4; mf++)
#pragma unroll
        for (int nf = 0; nf < 4; nf++) {
            const float* c = acc[mf][nf];
            size_t r0 = row0 + wm + mf * 16 + g;
            size_t cc = col0 + wn + nf * 8 + 2 * t;
            *(float2*)(outb + r0 * DIMN + cc)       = make_float2(c[0], c[1]);
            *(float2*)(outb + (r0 + 8) * DIMN + cc) = make_float2(c[2], c[3]);
        }

    // ---- softmax partials from registers ----
    float rm_[4][2], rs_[4][2];
#pragma unroll
    for (int mf = 0; mf < 4; mf++)
#pragma unroll
        for (int rh = 0; rh < 2; rh++) {
            float m = -1e30f;
#pragma unroll
            for (int nf = 0; nf < 4; nf++)
                m = fmaxf(m, fmaxf(acc[mf][nf][rh * 2], acc[mf][nf][rh * 2 + 1]));
            m = fmaxf(m, __shfl_xor_sync(0xffffffffu, m, 1));
            m = fmaxf(m, __shfl_xor_sync(0xffffffffu, m, 2));
            float s = 0.f;
#pragma unroll
            for (int nf = 0; nf < 4; nf++)
                s += __expf(acc[mf][nf][rh * 2] - m) + __expf(acc[mf][nf][rh * 2 + 1] - m);
            s += __shfl_xor_sync(0xffffffffu, s, 1);
            s += __shfl_xor_sync(0xffffffffu, s, 2);
            rm_[mf][rh] = m; rs_[mf][rh] = s;
        }
    float cm_[4][2], cs_[4][2];
#pragma unroll
    for (int nf = 0; nf < 4; nf++)
#pragma unroll
        for (int cr = 0; cr < 2; cr++) {
            float m = -1e30f;
#pragma unroll
            for (int mf = 0; mf < 4; mf++)
                m = fmaxf(m, fmaxf(acc[mf][nf][cr], acc[mf][nf][2 + cr]));
            m = fmaxf(m, __shfl_xor_sync(0xffffffffu, m, 4));
            m = fmaxf(m, __shfl_xor_sync(0xffffffffu, m, 8));
            m = fmaxf(m, __shfl_xor_sync(0xffffffffu, m, 16));
            float s = 0.f;
#pragma unroll
            for (int mf = 0; mf < 4; mf++)
                s += __expf(acc[mf][nf][cr] - m) + __expf(acc[mf][nf][2 + cr] - m);
            s += __shfl_xor_sync(0xffffffffu, s, 4);
            s += __shfl_xor_sync(0xffffffffu, s, 8);
            s += __shfl_xor_sync(0xffffffffu, s, 16);
            cm_[nf][cr] = m; cs_[nf][cr] = s;
        }

    __syncthreads();   // stage buffers dead; reuse smem for staging
    float* sRM = (float*)smem;        // [4][128]
    float* sRS = sRM + 512;
    float* sCM = sRS + 512;           // [2][128]
    float* sCS = sCM + 256;
    if (t == 0) {
#pragma unroll
        for (int mf = 0; mf < 4; mf++)
#pragma unroll
            for (int rh = 0; rh < 2; rh++) {
                int r = wm + mf * 16 + g + 8 * rh;
                sRM[(warp & 3) * 128 + r] = rm_[mf][rh];
                sRS[(warp & 3) * 128 + r] = rs_[mf][rh];
            }
    }
    if (g == 0) {
#pragma unroll
        for (int nf = 0; nf < 4; nf++)
#pragma unroll
            for (int cr = 0; cr < 2; cr++) {
                int c = wn + nf * 8 + 2 * t + cr;
                sCM[(warp >> 2) * 128 + c] = cm_[nf][cr];
                sCS[(warp >> 2) * 128 + c] = cs_[nf][cr];
            }
    }
    __syncthreads();
    if (tid < 128) {
        int r = tid;
        float m = -1e30f;
#pragma unroll
        for (int w = 0; w < 4; w++) m = fmaxf(m, sRM[w * 128 + r]);
        float s = 0.f;
#pragma unroll
        for (int w = 0; w < 4; w++) s += sRS[w * 128 + r] * __expf(sRM[w * 128 + r] - m);
        size_t ri = (z * DIMN + row0 + r) * 8 + blockIdx.x;
        rpm[ri] = m; rps[ri] = s;

        int c = tid;
        float mc = fmaxf(sCM[c], sCM[128 + c]);
        float sc = sCS[c] * __expf(sCM[c] - mc) + sCS[128 + c] * __expf(sCM[128 + c] - mc);
        size_t ci = (z * DIMN + col0 + c) * 8 + blockIdx.y;
        cpm[ci] = mc; cps[ci] = sc;
    }
}

// ---- single-output batched GEMM (M1 or M2 path), z in [0,4) ----
__global__ __launch_bounds__(256, 2)
void gemm_one(const __nv_bfloat16* __restrict__ Ah, const __nv_bfloat16* __restrict__ Al,
              const __nv_bfloat16* __restrict__ Bh, const __nv_bfloat16* __restrict__ Bl,
              float* __restrict__ o)
{
    extern __shared__ char smem[];
    const unsigned sb = smem_u32(smem);
    const int tid = threadIdx.x, warp = tid >> 5, lane = tid & 31;
    const int wm = (warp >> 2) * 64, wn = (warp & 3) * 32;
    const size_t z = blockIdx.z;
    const size_t row0 = (size_t)blockIdx.y * 128, col0 = (size_t)blockIdx.x * 128;

    GPtr p; unsigned so0, so1;
    make_gptr(p, so0, so1, Ah, Al, Bh, Bl, z * MATS, z * MATS, row0, col0, tid);
    float acc[4][4][4] = {};
    mainloop_s(sb, p, so0, so1, lane, wm, wn, acc);

    const int g = lane >> 2, t = lane & 3;
    float* outb = o + z * MATS;
#pragma unroll
    for (int mf = 0; mf < 4; mf++)
#pragma unroll
        for (int nf = 0; nf < 4; nf++) {
            const float* c = acc[mf][nf];
            size_t r0 = row0 + wm + mf * 16 + g;
            size_t cc = col0 + wn + nf * 8 + 2 * t;
            *(float2*)(outb + r0 * DIMN + cc)       = make_float2(c[0], c[1]);
            *(float2*)(outb + (r0 + 8) * DIMN + cc) = make_float2(c[2], c[3]);
        }
}

// ---------------- elementwise ----------------
__global__ __launch_bounds__(256)
void split_kernel(const float* __restrict__ in, __nv_bfloat16* __restrict__ h,
                  __nv_bfloat16* __restrict__ l)
{
    size_t i = (size_t)blockIdx.x * 256 + threadIdx.x;
    float4 v = ((const float4*)in)[i];
    union { __nv_bfloat16 b[4]; uint2 u; } H, L;
    bsplit(v.x, H.b[0], L.b[0]); bsplit(v.y, H.b[1], L.b[1]);
    bsplit(v.z, H.b[2], L.b[2]); bsplit(v.w, H.b[3], L.b[3]);
    ((uint2*)h)[i] = H.u;
    ((uint2*)l)[i] = L.u;
}

// fused: row-major split AND transposed split in one read of the input
__global__ __launch_bounds__(256)
void fsplit_kernel(const float* __restrict__ in,
                   __nv_bfloat16* __restrict__ h,  __nv_bfloat16* __restrict__ l,
                   __nv_bfloat16* __restrict__ th, __nv_bfloat16* __restrict__ tl_)
{
    __shared__ float tle[32][33];
    const int z = blockIdx.z;
    const float* src = in + (size_t)z * MATS;
    const int bx = blockIdx.x * 32, by = blockIdx.y * 32;
    const int x = threadIdx.x, y = threadIdx.y;   // block (32, 8)
#pragma unroll
    for (int i = 0; i < 4; i++) {
        int row = by + y + 8 * i;
        float v = src[(size_t)row * DIMN + bx + x];
        tle[y + 8 * i][x] = v;
        __nv_bfloat16 hh, ll;
        bsplit(v, hh, ll);
        size_t o = (size_t)z * MATS + (size_t)row * DIMN + bx + x;
        h[o] = hh; l[o] = ll;
    }
    __syncthreads();
#pragma unroll
    for (int i = 0; i < 4; i++) {
        int cI = bx + y + 8 * i;
        float v = tle[x][y + 8 * i];
        __nv_bfloat16 hh, ll;
        bsplit(v, hh, ll);
        size_t o = (size_t)z * MATS + (size_t)cI * DIMN + by + x;
        th[o] = hh; tl_[o] = ll;
    }
}

// combine 8 (max,sum) partials -> (max, 1/sum)
__global__ __launch_bounds__(256)
void combine_kernel(const float* __restrict__ pm, const float* __restrict__ ps,
                    float* __restrict__ omax, float* __restrict__ oinv)
{
    int idx = blockIdx.x * 256 + threadIdx.x;
    const float* m8 = pm + (size_t)idx * 8;
    const float* s8 = ps + (size_t)idx * 8;
    float m = -1e30f;
#pragma unroll
    for (int j = 0; j < 8; j++) m = fmaxf(m, m8[j]);
    float s = 0.f;
#pragma unroll
    for (int j = 0; j < 8; j++) s += s8[j] * __expf(m8[j] - m);
    omax[idx] = m;
    oinv[idx] = 1.0f / s;
}

// A1 = rowsoftmax(S) split (row-major, pure elementwise, coalesced)
__global__ __launch_bounds__(256)
void apply_row(const float* __restrict__ S,
               const float* __restrict__ rmax, const float* __restrict__ rinv,
               __nv_bfloat16* __restrict__ A1h, __nv_bfloat16* __restrict__ A1l)
{
    size_t i = (size_t)blockIdx.x * 256 + threadIdx.x;   // float4 units
    int row = (int)(i >> 8);
    float rm = rmax[row], ri = rinv[row];
    float4 v = ((const float4*)S)[i];
    union { __nv_bfloat16 b[4]; uint2 u; } H, L;
    bsplit(__expf(v.x - rm) * ri, H.b[0], L.b[0]);
    bsplit(__expf(v.y - rm) * ri, H.b[1], L.b[1]);
    bsplit(__expf(v.z - rm) * ri, H.b[2], L.b[2]);
    bsplit(__expf(v.w - rm) * ri, H.b[3], L.b[3]);
    ((uint2*)A1h)[i] = H.u;
    ((uint2*)A1l)[i] = L.u;
}

// A2T = colsoftmax(S)^T split (transpose tile kernel)
__global__ __launch_bounds__(256)
void apply_colT(const float* __restrict__ S,
                const float* __restrict__ cmax, const float* __restrict__ cinv,
                __nv_bfloat16* __restrict__ A2h, __nv_bfloat16* __restrict__ A2l)
{
    __shared__ float tle[32][33];
    const int z = blockIdx.z;
    const int bx = blockIdx.x * 32, by = blockIdx.y * 32;
    const int x = threadIdx.x, y = threadIdx.y;
    const float* Sp = S + (size_t)z * MATS;
#pragma unroll
    for (int i = 0; i < 4; i++)
        tle[y + 8 * i][x] = Sp[(size_t)(by + y + 8 * i) * DIMN + bx + x];
    __syncthreads();
#pragma unroll
    for (int i = 0; i < 4; i++) {
        int cI = bx + y + 8 * i;
        float v = tle[x][y + 8 * i];
        float val = __expf(v - cmax[z * DIMN + cI]) * cinv[z * DIMN + cI];
        __nv_bfloat16 hh, ll;
        bsplit(val, hh, ll);
        size_t o = (size_t)z * MATS + (size_t)cI * DIMN + by + x;
        A2h[o] = hh; A2l[o] = ll;
    }
}

// ---------------- capture-DAG helpers (no streams, no events) ----------------
static inline cudaGraphNode_t cap_tail() {
    cudaStreamCaptureStatus st = cudaStreamCaptureStatusNone;
    unsigned long long id = 0;
    cudaGraph_t gr = nullptr;
    const cudaGraphNode_t* deps = nullptr;
    const cudaGraphEdgeData* edges = nullptr;
    size_t nd = 0;
    cudaError_t e = cudaStreamGetCaptureInfo((cudaStream_t)0, &st, &id, &gr,
                                             &deps, &edges, &nd);
    if (e != cudaSuccess || st != cudaStreamCaptureStatusActive || nd < 1) {
        (void)cudaGetLastError();
        return nullptr;
    }
    return deps[nd - 1];
}
static inline void cap_set_deps(cudaGraphNode_t* nodes, size_t n) {
    if (!nodes || !nodes[0]) { (void)cudaGetLastError(); return; }
    (void)cudaStreamUpdateCaptureDependencies((cudaStream_t)0, nodes,
                                              (const cudaGraphEdgeData*)nullptr, n,
                                              cudaStreamSetCaptureDependencies);
    (void)cudaGetLastError();
}

// ---------------- launcher: fork-join DAG, split row/col tails ----------------
extern "C" void kernel_launch(void* const* d_in, const int* in_sizes, int n_in,
                              void* d_out, int out_size)
{
    const float* a1 = (const float*)d_in[0];
    const float* a2 = (const float*)d_in[1];
    const float* Gw = (const float*)d_in[2];
    const float* Gb = (const float*)d_in[3];
    float* M1 = (float*)d_out;
    float* M2 = M1 + TOT;

    __nv_bfloat16 *a1h, *a1l, *a2h, *a2l, *gwh, *gwl, *a2ph, *a2pl;
    __nv_bfloat16 *A1h, *A1l, *A2h, *A2l, *a2Th, *a2Tl, *a1Th, *a1Tl;
    float *S, *rmax, *rinv, *cmax, *cinv, *rpm, *rps, *cpm, *cps;
    cudaGetSymbolAddress((void**)&a1h, g_a1h);   cudaGetSymbolAddress((void**)&a1l, g_a1l);
    cudaGetSymbolAddress((void**)&a2h, g_a2h);   cudaGetSymbolAddress((void**)&a2l, g_a2l);
    cudaGetSymbolAddress((void**)&gwh, g_gwh);   cudaGetSymbolAddress((void**)&gwl, g_gwl);
    cudaGetSymbolAddress((void**)&a2ph, g_a2ph); cudaGetSymbolAddress((void**)&a2pl, g_a2pl);
    cudaGetSymbolAddress((void**)&A1h, g_A1h);   cudaGetSymbolAddress((void**)&A1l, g_A1l);
    cudaGetSymbolAddress((void**)&A2h, g_A2h);   cudaGetSymbolAddress((void**)&A2l, g_A2l);
    cudaGetSymbolAddress((void**)&a2Th, g_a2Th); cudaGetSymbolAddress((void**)&a2Tl, g_a2Tl);
    cudaGetSymbolAddress((void**)&a1Th, g_a1Th); cudaGetSymbolAddress((void**)&a1Tl, g_a1Tl);
    cudaGetSymbolAddress((void**)&S, g_S);
    cudaGetSymbolAddress((void**)&rmax, g_rmax); cudaGetSymbolAddress((void**)&rinv, g_rinv);
    cudaGetSymbolAddress((void**)&cmax, g_cmax); cudaGetSymbolAddress((void**)&cinv, g_cinv);
    cudaGetSymbolAddress((void**)&rpm, g_rpm);   cudaGetSymbolAddress((void**)&rps, g_rps);
    cudaGetSymbolAddress((void**)&cpm, g_cpm);   cudaGetSymbolAddress((void**)&cps, g_cps);

    cudaFuncSetAttribute(gemm_a2p, cudaFuncAttributeMaxDynamicSharedMemorySize, SMEM_TOT);
    cudaFuncSetAttribute(gemm_S,   cudaFuncAttributeMaxDynamicSharedMemorySize, SMEM_TOT);
    cudaFuncSetAttribute(gemm_one, cudaFuncAttributeMaxDynamicSharedMemorySize, SMEM_TOT);

    // root: Gw split (fork point for all 4 chains)
    split_kernel<<<1024, 256>>>(Gw, gwh, gwl);
    cudaGraphNode_t nGw = cap_tail();

    cudaGraphNode_t nTail[8] = {};
    for (int grp = 0; grp < 4; grp++) {
        const size_t mo = (size_t)grp * 4 * MATS;      // matrix offset (4 batches)
        const size_t vo = (size_t)grp * 4 * DIMN;      // vector offset
        const size_t po = vo * 8;                       // partials offset

        // fork: both fsplits depend only on the Gw-split node
        cap_set_deps(&nGw, 1);
        fsplit_kernel<<<dim3(32, 32, 4), dim3(32, 8)>>>(
            a2 + mo, a2h + mo, a2l + mo, a2Th + mo, a2Tl + mo);
        cudaGraphNode_t nF2 = cap_tail();

        cap_set_deps(&nGw, 1);
        fsplit_kernel<<<dim3(32, 32, 4), dim3(32, 8)>>>(
            a1 + mo, a1h + mo, a1l + mo, a1Th + mo, a1Tl + mo);
        cudaGraphNode_t nF1 = cap_tail();

        // a2p depends on fsplit(a2)
        cap_set_deps(&nF2, 1);
        gemm_a2p<<<dim3(8, 32, 1), 256, SMEM_TOT>>>(
            a2h + mo, a2l + mo, gwh, gwl, a2ph + mo, a2pl + mo, Gb);
        cudaGraphNode_t nA2p = cap_tail();

        // S depends on fsplit(a1) + a2p
        {
            cudaGraphNode_t d2[2] = { nF1, nA2p };
            cap_set_deps(d2, (nF1 && nA2p) ? 2 : 1);
        }
        gemm_S<<<dim3(8, 8, 4), 256, SMEM_TOT>>>(
            a1h + mo, a1l + mo, a2ph + mo, a2pl + mo, S + mo,
            rpm + po, rps + po, cpm + po, cps + po);
        cudaGraphNode_t nS = cap_tail();

        // --- row path: combine_r -> applyA1 -> gemm M1 ---
        combine_kernel<<<16, 256>>>(rpm + po, rps + po, rmax + vo, rinv + vo);
        apply_row<<<4096, 256>>>(S + mo, rmax + vo, rinv + vo, A1h + mo, A1l + mo);
        gemm_one<<<dim3(8, 8, 4), 256, SMEM_TOT>>>(
            A1h + mo, A1l + mo, a2Th + mo, a2Tl + mo, M1 + mo);
        nTail[grp * 2] = cap_tail();

        // --- col path: combine_c -> applyA2T -> gemm M2 (fork from S) ---
        cap_set_deps(&nS, 1);
        combine_kernel<<<16, 256>>>(cpm + po, cps + po, cmax + vo, cinv + vo);
        apply_colT<<<dim3(32, 32, 4), dim3(32, 8)>>>(
            S + mo, cmax + vo, cinv + vo, A2h + mo, A2l + mo);
        gemm_one<<<dim3(8, 8, 4), 256, SMEM_TOT>>>(
            A2h + mo, A2l + mo, a1Th + mo, a1Tl + mo, M2 + mo);
        nTail[grp * 2 + 1] = cap_tail();
    }

    // join: subsequent captured work depends on all chain tails
    bool all = true;
    for (int i = 0; i < 8; i++) all = all && (nTail[i] != nullptr);
    if (all) cap_set_deps(nTail, 8);
}

// round 16
// speedup vs baseline: 1.0725x; 1.0002x over previous
#include <cuda_runtime.h>
#include <cuda_bf16.h>

#define DIMN 1024
#define NB 16
#define MATS ((size_t)DIMN * DIMN)     /* 1M  */
#define TOT  ((size_t)NB * MATS)       /* 16M */

// ---------------- scratch (device globals; allocation-free) ----------------
__device__ __nv_bfloat16 g_a1h[TOT],  g_a1l[TOT];
__device__ __nv_bfloat16 g_a2h[TOT],  g_a2l[TOT];
__device__ __nv_bfloat16 g_gwh[MATS], g_gwl[MATS];
__device__ __nv_bfloat16 g_a2ph[TOT], g_a2pl[TOT];
__device__ float         g_S[TOT];
__device__ __nv_bfloat16 g_A1h[TOT],  g_A1l[TOT];     // rowsoftmax(S)
__device__ __nv_bfloat16 g_A2h[TOT],  g_A2l[TOT];     // colsoftmax(S)^T
__device__ __nv_bfloat16 g_a2Th[TOT], g_a2Tl[TOT];    // a2^T
__device__ __nv_bfloat16 g_a1Th[TOT], g_a1Tl[TOT];    // a1^T
__device__ float g_rmax[NB * DIMN], g_rinv[NB * DIMN];
__device__ float g_cmax[NB * DIMN], g_cinv[NB * DIMN];
__device__ float g_rpm[NB * 8 * DIMN], g_rps[NB * 8 * DIMN];
__device__ float g_cpm[NB * 8 * DIMN], g_cps[NB * 8 * DIMN];

// ---------------- helpers ----------------
__device__ __forceinline__ unsigned smem_u32(const void* p) {
    unsigned r;
    asm("{ .reg .u64 t; cvta.to.shared.u64 t, %1; cvt.u32.u64 %0, t; }"
        : "=r"(r) : "l"(p));
    return r;
}
__device__ __forceinline__ unsigned swz64(unsigned x) { return x ^ ((x >> 3) & 0x30); }

__device__ __forceinline__ void bsplit(float v, __nv_bfloat16& h, __nv_bfloat16& l) {
    h = __float2bfloat16_rn(v);
    l = __float2bfloat16_rn(v - __bfloat162float(h));
}

#define CP16(dst, src) \
    asm volatile("cp.async.cg.shared.global [%0], [%1], 16;" :: "r"(dst), "l"(src))

#define LDSM4(r, addr) \
    asm volatile("ldmatrix.sync.aligned.m8n8.x4.shared.b16 {%0,%1,%2,%3}, [%4];" \
        : "=r"((r)[0]), "=r"((r)[1]), "=r"((r)[2]), "=r"((r)[3]) : "r"(addr))

#define MMA16816(c, a, b)                                                      \
    asm volatile("mma.sync.aligned.m16n8k16.row.col.f32.bf16.bf16.f32 "        \
        "{%0,%1,%2,%3}, {%4,%5,%6,%7}, {%8,%9}, {%0,%1,%2,%3};"                \
        : "+f"((c)[0]), "+f"((c)[1]), "+f"((c)[2]), "+f"((c)[3])               \
        : "r"((a)[0]), "r"((a)[1]), "r"((a)[2]), "r"((a)[3]),                  \
          "r"((b)[0]), "r"((b)[1]))

// ================= bf16 3-term NT GEMM core (R5-proven) ====================
// CTA 128x128, BK=32, 3-stage, 256 thr, 8 warps (2x4), warp 64x32.
// Mainloop unrolled x3 so stage offsets are compile-time per copy.
#define STAGE_B   32768
#define SMEM_TOT  (3 * STAGE_B)

struct GPtr { const char *ah, *al, *bh, *bl; };

__device__ __forceinline__ void issue_loads_s(unsigned st, const GPtr& p, unsigned kbyte,
                                              unsigned so0, unsigned so1) {
    const unsigned RS = 64u * DIMN * 2u;
    CP16(st +     0 + so0, p.ah + kbyte);
    CP16(st +     0 + so1, p.ah + kbyte + RS);
    CP16(st +  8192 + so0, p.al + kbyte);
    CP16(st +  8192 + so1, p.al + kbyte + RS);
    CP16(st + 16384 + so0, p.bh + kbyte);
    CP16(st + 16384 + so1, p.bh + kbyte + RS);
    CP16(st + 24576 + so0, p.bl + kbyte);
    CP16(st + 24576 + so1, p.bl + kbyte + RS);
    asm volatile("cp.async.commit_group;" ::: "memory");
}

__device__ __forceinline__ void mma_stage(unsigned st, int lane, int wm, int wn,
                                          float (*acc)[4][4])
{
#pragma unroll
    for (int ks = 0; ks < 2; ks++) {
        const unsigned kb = ks * 32;
        unsigned bh[8], bl[8];
#pragma unroll
        for (int nt = 0; nt < 2; nt++) {
            unsigned brow = wn + nt * 16 + (lane & 7) + ((lane >> 4) & 1) * 8;
            unsigned bb   = kb + ((lane >> 3) & 1) * 16;
            unsigned ba   = st + 16384 + swz64(brow * 64 + bb);
            LDSM4(bh + nt * 4, ba);
            LDSM4(bl + nt * 4, ba + 8192);
        }
#pragma unroll
        for (int mf = 0; mf < 4; mf++) {
            unsigned arow = wm + mf * 16 + (lane & 15);
            unsigned ab   = kb + ((lane >> 4) & 1) * 16;
            unsigned aa   = st + swz64(arow * 64 + ab);
            unsigned ah[4], al[4];
            LDSM4(ah, aa);
            LDSM4(al, aa + 8192);
#pragma unroll
            for (int nf = 0; nf < 4; nf++) {
                MMA16816(acc[mf][nf], ah, bh + nf * 2);
                MMA16816(acc[mf][nf], ah, bl + nf * 2);
                MMA16816(acc[mf][nf], al, bh + nf * 2);
            }
        }
    }
}

__device__ __forceinline__ void mainloop_s(unsigned sb, const GPtr& p,
                                           unsigned so0, unsigned so1,
                                           int lane, int wm, int wn,
                                           float (*acc)[4][4])
{
    issue_loads_s(sb,           p, 0,  so0, so1);
    issue_loads_s(sb + STAGE_B, p, 64, so0, so1);

#pragma unroll 3
    for (int it = 0; it < 32; it++) {
        if (it < 31) asm volatile("cp.async.wait_group 1;" ::: "memory");
        else         asm volatile("cp.async.wait_group 0;" ::: "memory");
        __syncthreads();
        if (it + 2 < 32) {
            unsigned wst = sb + (unsigned)((it + 2) % 3) * STAGE_B;
            issue_loads_s(wst, p, (unsigned)(it + 2) * 64, so0, so1);
        }
        mma_stage(sb + (unsigned)(it % 3) * STAGE_B, lane, wm, wn, acc);
    }
}

__device__ __forceinline__ void make_gptr(GPtr& p, unsigned& so0, unsigned& so1,
    const __nv_bfloat16* Ah, const __nv_bfloat16* Al,
    const __nv_bfloat16* Bh, const __nv_bfloat16* Bl,
    size_t zA, size_t zB, size_t row0, size_t col0, int tid)
{
    size_t ar = row0 + (tid >> 2);
    size_t br = col0 + (tid >> 2);
    size_t ko = (size_t)(tid & 3) * 8;
    p.ah = (const char*)Ah + (zA + ar * DIMN + ko) * 2;
    p.al = (const char*)Al + (zA + ar * DIMN + ko) * 2;
    p.bh = (const char*)Bh + (zB + br * DIMN + ko) * 2;
    p.bl = (const char*)Bl + (zB + br * DIMN + ko) * 2;
    so0 = swz64(((unsigned)(tid >> 2)) * 64 + (tid & 3) * 16);
    so1 = so0 + 4096;
}

// ---- a2p GEMM: bias add + split bf16 pair out ----
__global__ __launch_bounds__(256, 2)
void gemm_a2p(const __nv_bfloat16* __restrict__ Ah, const __nv_bfloat16* __restrict__ Al,
              const __nv_bfloat16* __restrict__ Bh, const __nv_bfloat16* __restrict__ Bl,
              __nv_bfloat16* __restrict__ outH, __nv_bfloat16* __restrict__ outL,
              const float* __restrict__ bias)
{
    extern __shared__ char smem[];
    const unsigned sb = smem_u32(smem);
    const int tid = threadIdx.x, warp = tid >> 5, lane = tid & 31;
    const int wm = (warp >> 2) * 64, wn = (warp & 3) * 32;
    const size_t row0 = (size_t)blockIdx.y * 128, col0 = (size_t)blockIdx.x * 128;

    GPtr p; unsigned so0, so1;
    make_gptr(p, so0, so1, Ah, Al, Bh, Bl, 0, 0, row0, col0, tid);
    float acc[4][4][4] = {};
    mainloop_s(sb, p, so0, so1, lane, wm, wn, acc);

    const int g = lane >> 2, t = lane & 3;
#pragma unroll
    for (int mf = 0; mf < 4; mf++)
#pragma unroll
        for (int nf = 0; nf < 4; nf++) {
            const float* c = acc[mf][nf];
            size_t r0 = row0 + wm + mf * 16 + g;
            size_t cc = col0 + wn + nf * 8 + 2 * t;
            float b0 = bias[cc], b1 = bias[cc + 1];
            union { __nv_bfloat16 b[2]; unsigned u; } H0, L0, H1, L1;
            bsplit(c[0] + b0, H0.b[0], L0.b[0]);
            bsplit(c[1] + b1, H0.b[1], L0.b[1]);
            bsplit(c[2] + b0, H1.b[0], L1.b[0]);
            bsplit(c[3] + b1, H1.b[1], L1.b[1]);
            *(unsigned*)(outH + r0 * DIMN + cc)       = H0.u;
            *(unsigned*)(outL + r0 * DIMN + cc)       = L0.u;
            *(unsigned*)(outH + (r0 + 8) * DIMN + cc) = H1.u;
            *(unsigned*)(outL + (r0 + 8) * DIMN + cc) = L1.u;
        }
}

// ---- S GEMM: fp32 out + fused per-CTA row/col softmax partials ----
__global__ __launch_bounds__(256, 2)
void gemm_S(const __nv_bfloat16* __restrict__ Ah, const __nv_bfloat16* __restrict__ Al,
            const __nv_bfloat16* __restrict__ Bh, const __nv_bfloat16* __restrict__ Bl,
            float* __restrict__ outF,
            float* __restrict__ rpm, float* __restrict__ rps,
            float* __restrict__ cpm, float* __restrict__ cps)
{
    extern __shared__ char smem[];
    const unsigned sb = smem_u32(smem);
    const int tid = threadIdx.x, warp = tid >> 5, lane = tid & 31;
    const int wm = (warp >> 2) * 64, wn = (warp & 3) * 32;
    const size_t z = blockIdx.z;
    const size_t row0 = (size_t)blockIdx.y * 128, col0 = (size_t)blockIdx.x * 128;

    GPtr p; unsigned so0, so1;
    make_gptr(p, so0, so1, Ah, Al, Bh, Bl, z * MATS, z * MATS, row0, col0, tid);
    float acc[4][4][4] = {};
    mainloop_s(sb, p, so0, so1, lane, wm, wn, acc);

    const int g = lane >> 2, t = lane & 3;
    float* outb = outF + z * MATS;
#pragma unroll
    for (int mf = 0; mf < 4; mf++)
#pragma unroll
        for (int nf = 0; nf < 4; nf++) {
            const float* c = acc[mf][nf];
            size_t r0 = row0 + wm + mf * 16 + g;
            size_t cc = col0 + wn + nf * 8 + 2 * t;
            *(float2*)(outb + r0 * DIMN + cc)       = make_float2(c[0], c[1]);
            *(float2*)(outb + (r0 + 8) * DIMN + cc) = make_float2(c[2], c[3]);
        }

    // ---- softmax partials from registers ----
    float rm_[4][2], rs_[4][2];
#pragma unroll
    for (int mf = 0; mf < 4; mf++)
#pragma unroll
        for (int rh = 0; rh < 2; rh++) {
            float m = -1e30f;
#pragma unroll
            for (int nf = 0; nf < 4; nf++)
                m = fmaxf(m, fmaxf(acc[mf][nf][rh * 2], acc[mf][nf][rh * 2 + 1]));
            m = fmaxf(m, __shfl_xor_sync(0xffffffffu, m, 1));
            m = fmaxf(m, __shfl_xor_sync(0xffffffffu, m, 2));
            float s = 0.f;
#pragma unroll
            for (int nf = 0; nf < 4; nf++)
                s += __expf(acc[mf][nf][rh * 2] - m) + __expf(acc[mf][nf][rh * 2 + 1] - m);
            s += __shfl_xor_sync(0xffffffffu, s, 1);
            s += __shfl_xor_sync(0xffffffffu, s, 2);
            rm_[mf][rh] = m; rs_[mf][rh] = s;
        }
    float cm_[4][2], cs_[4][2];
#pragma unroll
    for (int nf = 0; nf < 4; nf++)
#pragma unroll
        for (int cr = 0; cr < 2; cr++) {
            float m = -1e30f;
#pragma unroll
            for (int mf = 0; mf < 4; mf++)
                m = fmaxf(m, fmaxf(acc[mf][nf][cr], acc[mf][nf][2 + cr]));
            m = fmaxf(m, __shfl_xor_sync(0xffffffffu, m, 4));
            m = fmaxf(m, __shfl_xor_sync(0xffffffffu, m, 8));
            m = fmaxf(m, __shfl_xor_sync(0xffffffffu, m, 16));
            float s = 0.f;
#pragma unroll
            for (int mf = 0; mf < 4; mf++)
                s += __expf(acc[mf][nf][cr] - m) + __expf(acc[mf][nf][2 + cr] - m);
            s += __shfl_xor_sync(0xffffffffu, s, 4);
            s += __shfl_xor_sync(0xffffffffu, s, 8);
            s += __shfl_xor_sync(0xffffffffu, s, 16);
            cm_[nf][cr] = m; cs_[nf][cr] = s;
        }

    __syncthreads();   // stage buffers dead; reuse smem for staging
    float* sRM = (float*)smem;        // [4][128]
    float* sRS = sRM + 512;
    float* sCM = sRS + 512;           // [2][128]
    float* sCS = sCM + 256;
    if (t == 0) {
#pragma unroll
        for (int mf = 0; mf < 4; mf++)
#pragma unroll
            for (int rh = 0; rh < 2; rh++) {
                int r = wm + mf * 16 + g + 8 * rh;
                sRM[(warp & 3) * 128 + r] = rm_[mf][rh];
                sRS[(warp & 3) * 128 + r] = rs_[mf][rh];
            }
    }
    if (g == 0) {
#pragma unroll
        for (int nf = 0; nf < 4; nf++)
#pragma unroll
            for (int cr = 0; cr < 2; cr++) {
                int c = wn + nf * 8 + 2 * t + cr;
                sCM[(warp >> 2) * 128 + c] = cm_[nf][cr];
                sCS[(warp >> 2) * 128 + c] = cs_[nf][cr];
            }
    }
    __syncthreads();
    if (tid < 128) {
        int r = tid;
        float m = -1e30f;
#pragma unroll
        for (int w = 0; w < 4; w++) m = fmaxf(m, sRM[w * 128 + r]);
        float s = 0.f;
#pragma unroll
        for (int w = 0; w < 4; w++) s += sRS[w * 128 + r] * __expf(sRM[w * 128 + r] - m);
        size_t ri = (z * DIMN + row0 + r) * 8 + blockIdx.x;
        rpm[ri] = m; rps[ri] = s;

        int c = tid;
        float mc = fmaxf(sCM[c], sCM[128 + c]);
        float sc = sCS[c] * __expf(sCM[c] - mc) + sCS[128 + c] * __expf(sCM[128 + c] - mc);
        size_t ci = (z * DIMN + col0 + c) * 8 + blockIdx.y;
        cpm[ci] = mc; cps[ci] = sc;
    }
}

// ---- single-output batched GEMM (M1 or M2 path), z in [0,4) ----
__global__ __launch_bounds__(256, 2)
void gemm_one(const __nv_bfloat16* __restrict__ Ah, const __nv_bfloat16* __restrict__ Al,
              const __nv_bfloat16* __restrict__ Bh, const __nv_bfloat16* __restrict__ Bl,
              float* __restrict__ o)
{
    extern __shared__ char smem[];
    const unsigned sb = smem_u32(smem);
    const int tid = threadIdx.x, warp = tid >> 5, lane = tid & 31;
    const int wm = (warp >> 2) * 64, wn = (warp & 3) * 32;
    const size_t z = blockIdx.z;
    const size_t row0 = (size_t)blockIdx.y * 128, col0 = (size_t)blockIdx.x * 128;

    GPtr p; unsigned so0, so1;
    make_gptr(p, so0, so1, Ah, Al, Bh, Bl, z * MATS, z * MATS, row0, col0, tid);
    float acc[4][4][4] = {};
    mainloop_s(sb, p, so0, so1, lane, wm, wn, acc);

    const int g = lane >> 2, t = lane & 3;
    float* outb = o + z * MATS;
#pragma unroll
    for (int mf = 0; mf < 4; mf++)
#pragma unroll
        for (int nf = 0; nf < 4; nf++) {
            const float* c = acc[mf][nf];
            size_t r0 = row0 + wm + mf * 16 + g;
            size_t cc = col0 + wn + nf * 8 + 2 * t;
            *(float2*)(outb + r0 * DIMN + cc)       = make_float2(c[0], c[1]);
            *(float2*)(outb + (r0 + 8) * DIMN + cc) = make_float2(c[2], c[3]);
        }
}

// ---------------- elementwise ----------------
__global__ __launch_bounds__(256)
void split_kernel(const float* __restrict__ in, __nv_bfloat16* __restrict__ h,
                  __nv_bfloat16* __restrict__ l)
{
    size_t i = (size_t)blockIdx.x * 256 + threadIdx.x;
    float4 v = ((const float4*)in)[i];
    union { __nv_bfloat16 b[4]; uint2 u; } H, L;
    bsplit(v.x, H.b[0], L.b[0]); bsplit(v.y, H.b[1], L.b[1]);
    bsplit(v.z, H.b[2], L.b[2]); bsplit(v.w, H.b[3], L.b[3]);
    ((uint2*)h)[i] = H.u;
    ((uint2*)l)[i] = L.u;
}

// fused: row-major split AND transposed split in one read of the input
__global__ __launch_bounds__(256)
void fsplit_kernel(const float* __restrict__ in,
                   __nv_bfloat16* __restrict__ h,  __nv_bfloat16* __restrict__ l,
                   __nv_bfloat16* __restrict__ th, __nv_bfloat16* __restrict__ tl_)
{
    __shared__ float tle[32][33];
    const int z = blockIdx.z;
    const float* src = in + (size_t)z * MATS;
    const int bx = blockIdx.x * 32, by = blockIdx.y * 32;
    const int x = threadIdx.x, y = threadIdx.y;   // block (32, 8)
#pragma unroll
    for (int i = 0; i < 4; i++) {
        int row = by + y + 8 * i;
        float v = src[(size_t)row * DIMN + bx + x];
        tle[y + 8 * i][x] = v;
        __nv_bfloat16 hh, ll;
        bsplit(v, hh, ll);
        size_t o = (size_t)z * MATS + (size_t)row * DIMN + bx + x;
        h[o] = hh; l[o] = ll;
    }
    __syncthreads();
#pragma unroll
    for (int i = 0; i < 4; i++) {
        int cI = bx + y + 8 * i;
        float v = tle[x][y + 8 * i];
        __nv_bfloat16 hh, ll;
        bsplit(v, hh, ll);
        size_t o = (size_t)z * MATS + (size_t)cI * DIMN + by + x;
        th[o] = hh; tl_[o] = ll;
    }
}

// combine 8 (max,sum) partials -> (max, 1/sum)
__global__ __launch_bounds__(256)
void combine_kernel(const float* __restrict__ pm, const float* __restrict__ ps,
                    float* __restrict__ omax, float* __restrict__ oinv)
{
    int idx = blockIdx.x * 256 + threadIdx.x;
    const float* m8 = pm + (size_t)idx * 8;
    const float* s8 = ps + (size_t)idx * 8;
    float m = -1e30f;
#pragma unroll
    for (int j = 0; j < 8; j++) m = fmaxf(m, m8[j]);
    float s = 0.f;
#pragma unroll
    for (int j = 0; j < 8; j++) s += s8[j] * __expf(m8[j] - m);
    omax[idx] = m;
    oinv[idx] = 1.0f / s;
}

// A1 = rowsoftmax(S) split (row-major, pure elementwise, coalesced)
__global__ __launch_bounds__(256)
void apply_row(const float* __restrict__ S,
               const float* __restrict__ rmax, const float* __restrict__ rinv,
               __nv_bfloat16* __restrict__ A1h, __nv_bfloat16* __restrict__ A1l)
{
    size_t i = (size_t)blockIdx.x * 256 + threadIdx.x;   // float4 units
    int row = (int)(i >> 8);
    float rm = rmax[row], ri = rinv[row];
    float4 v = ((const float4*)S)[i];
    union { __nv_bfloat16 b[4]; uint2 u; } H, L;
    bsplit(__expf(v.x - rm) * ri, H.b[0], L.b[0]);
    bsplit(__expf(v.y - rm) * ri, H.b[1], L.b[1]);
    bsplit(__expf(v.z - rm) * ri, H.b[2], L.b[2]);
    bsplit(__expf(v.w - rm) * ri, H.b[3], L.b[3]);
    ((uint2*)A1h)[i] = H.u;
    ((uint2*)A1l)[i] = L.u;
}

// A2T = colsoftmax(S)^T split (transpose tile kernel)
__global__ __launch_bounds__(256)
void apply_colT(const float* __restrict__ S,
                const float* __restrict__ cmax, const float* __restrict__ cinv,
                __nv_bfloat16* __restrict__ A2h, __nv_bfloat16* __restrict__ A2l)
{
    __shared__ float tle[32][33];
    const int z = blockIdx.z;
    const int bx = blockIdx.x * 32, by = blockIdx.y * 32;
    const int x = threadIdx.x, y = threadIdx.y;
    const float* Sp = S + (size_t)z * MATS;
#pragma unroll
    for (int i = 0; i < 4; i++)
        tle[y + 8 * i][x] = Sp[(size_t)(by + y + 8 * i) * DIMN + bx + x];
    __syncthreads();
#pragma unroll
    for (int i = 0; i < 4; i++) {
        int cI = bx + y + 8 * i;
        float v = tle[x][y + 8 * i];
        float val = __expf(v - cmax[z * DIMN + cI]) * cinv[z * DIMN + cI];
        __nv_bfloat16 hh, ll;
        bsplit(val, hh, ll);
        size_t o = (size_t)z * MATS + (size_t)cI * DIMN + by + x;
        A2h[o] = hh; A2l[o] = ll;
    }
}

// ---------------- capture-DAG helpers (no streams, no events) ----------------
static inline cudaGraphNode_t cap_tail() {
    cudaStreamCaptureStatus st = cudaStreamCaptureStatusNone;
    unsigned long long id = 0;
    cudaGraph_t gr = nullptr;
    const cudaGraphNode_t* deps = nullptr;
    const cudaGraphEdgeData* edges = nullptr;
    size_t nd = 0;
    cudaError_t e = cudaStreamGetCaptureInfo((cudaStream_t)0, &st, &id, &gr,
                                             &deps, &edges, &nd);
    if (e != cudaSuccess || st != cudaStreamCaptureStatusActive || nd < 1) {
        (void)cudaGetLastError();
        return nullptr;
    }
    return deps[nd - 1];
}
static inline void cap_set_deps(cudaGraphNode_t* nodes, size_t n) {
    if (!nodes || !nodes[0]) { (void)cudaGetLastError(); return; }
    (void)cudaStreamUpdateCaptureDependencies((cudaStream_t)0, nodes,
                                              (const cudaGraphEdgeData*)nullptr, n,
                                              cudaStreamSetCaptureDependencies);
    (void)cudaGetLastError();
}

// ---------------- launcher: fork-join DAG, split row/col tails ----------------
extern "C" void kernel_launch(void* const* d_in, const int* in_sizes, int n_in,
                              void* d_out, int out_size)
{
    const float* a1 = (const float*)d_in[0];
    const float* a2 = (const float*)d_in[1];
    const float* Gw = (const float*)d_in[2];
    const float* Gb = (const float*)d_in[3];
    float* M1 = (float*)d_out;
    float* M2 = M1 + TOT;

    __nv_bfloat16 *a1h, *a1l, *a2h, *a2l, *gwh, *gwl, *a2ph, *a2pl;
    __nv_bfloat16 *A1h, *A1l, *A2h, *A2l, *a2Th, *a2Tl, *a1Th, *a1Tl;
    float *S, *rmax, *rinv, *cmax, *cinv, *rpm, *rps, *cpm, *cps;
    cudaGetSymbolAddress((void**)&a1h, g_a1h);   cudaGetSymbolAddress((void**)&a1l, g_a1l);
    cudaGetSymbolAddress((void**)&a2h, g_a2h);   cudaGetSymbolAddress((void**)&a2l, g_a2l);
    cudaGetSymbolAddress((void**)&gwh, g_gwh);   cudaGetSymbolAddress((void**)&gwl, g_gwl);
    cudaGetSymbolAddress((void**)&a2ph, g_a2ph); cudaGetSymbolAddress((void**)&a2pl, g_a2pl);
    cudaGetSymbolAddress((void**)&A1h, g_A1h);   cudaGetSymbolAddress((void**)&A1l, g_A1l);
    cudaGetSymbolAddress((void**)&A2h, g_A2h);   cudaGetSymbolAddress((void**)&A2l, g_A2l);
    cudaGetSymbolAddress((void**)&a2Th, g_a2Th); cudaGetSymbolAddress((void**)&a2Tl, g_a2Tl);
    cudaGetSymbolAddress((void**)&a1Th, g_a1Th); cudaGetSymbolAddress((void**)&a1Tl, g_a1Tl);
    cudaGetSymbolAddress((void**)&S, g_S);
    cudaGetSymbolAddress((void**)&rmax, g_rmax); cudaGetSymbolAddress((void**)&rinv, g_rinv);
    cudaGetSymbolAddress((void**)&cmax, g_cmax); cudaGetSymbolAddress((void**)&cinv, g_cinv);
    cudaGetSymbolAddress((void**)&rpm, g_rpm);   cudaGetSymbolAddress((void**)&rps, g_rps);
    cudaGetSymbolAddress((void**)&cpm, g_cpm);   cudaGetSymbolAddress((void**)&cps, g_cps);

    cudaFuncSetAttribute(gemm_a2p, cudaFuncAttributeMaxDynamicSharedMemorySize, SMEM_TOT);
    cudaFuncSetAttribute(gemm_S,   cudaFuncAttributeMaxDynamicSharedMemorySize, SMEM_TOT);
    cudaFuncSetAttribute(gemm_one, cudaFuncAttributeMaxDynamicSharedMemorySize, SMEM_TOT);

    // root: Gw split (fork point for all 4 chains)
    split_kernel<<<1024, 256>>>(Gw, gwh, gwl);
    cudaGraphNode_t nGw = cap_tail();

    cudaGraphNode_t nTail[8] = {};
    for (int grp = 0; grp < 4; grp++) {
        const size_t mo = (size_t)grp * 4 * MATS;      // matrix offset (4 batches)
        const size_t vo = (size_t)grp * 4 * DIMN;      // vector offset
        const size_t po = vo * 8;                       // partials offset

        // fork: both fsplits depend only on the Gw-split node
        cap_set_deps(&nGw, 1);
        fsplit_kernel<<<dim3(32, 32, 4), dim3(32, 8)>>>(
            a2 + mo, a2h + mo, a2l + mo, a2Th + mo, a2Tl + mo);
        cudaGraphNode_t nF2 = cap_tail();

        cap_set_deps(&nGw, 1);
        fsplit_kernel<<<dim3(32, 32, 4), dim3(32, 8)>>>(
            a1 + mo, a1h + mo, a1l + mo, a1Th + mo, a1Tl + mo);
        cudaGraphNode_t nF1 = cap_tail();

        // a2p depends on fsplit(a2)
        cap_set_deps(&nF2, 1);
        gemm_a2p<<<dim3(8, 32, 1), 256, SMEM_TOT>>>(
            a2h + mo, a2l + mo, gwh, gwl, a2ph + mo, a2pl + mo, Gb);
        cudaGraphNode_t nA2p = cap_tail();

        // S depends on fsplit(a1) + a2p
        {
            cudaGraphNode_t d2[2] = { nF1, nA2p };
            cap_set_deps(d2, (nF1 && nA2p) ? 2 : 1);
        }
        gemm_S<<<dim3(8, 8, 4), 256, SMEM_TOT>>>(
            a1h + mo, a1l + mo, a2ph + mo, a2pl + mo, S + mo,
            rpm + po, rps + po, cpm + po, cps + po);
        cudaGraphNode_t nS = cap_tail();

        // --- row path: combine_r -> applyA1 -> gemm M1 ---
        combine_kernel<<<16, 256>>>(rpm + po, rps + po, rmax + vo, rinv + vo);
        apply_row<<<4096, 256>>>(S + mo, rmax + vo, rinv + vo, A1h + mo, A1l + mo);
        gemm_one<<<dim3(8, 8, 4), 256, SMEM_TOT>>>(
            A1h + mo, A1l + mo, a2Th + mo, a2Tl + mo, M1 + mo);
        nTail[grp * 2] = cap_tail();

        // --- col path: combine_c -> applyA2T -> gemm M2 (fork from S) ---
        cap_set_deps(&nS, 1);
        combine_kernel<<<16, 256>>>(cpm + po, cps + po, cmax + vo, cinv + vo);
        apply_colT<<<dim3(32, 32, 4), dim3(32, 8)>>>(
            S + mo, cmax + vo, cinv + vo, A2h + mo, A2l + mo);
        gemm_one<<<dim3(8, 8, 4), 256, SMEM_TOT>>>(
            A2h + mo, A2l + mo, a1Th + mo, a1Tl + mo, M2 + mo);
        nTail[grp * 2 + 1] = cap_tail();
    }

    // join: subsequent captured work depends on all chain tails
    bool all = true;
    for (int i = 0; i < 8; i++) all = all && (nTail[i] != nullptr);
    if (all) cap_set_deps(nTail, 8);
}

// round 17
// speedup vs baseline: 1.1013x; 1.0269x over previous
#include <cuda_runtime.h>
#include <cuda_bf16.h>

#define DIMN 1024
#define NB 16
#define MATS ((size_t)DIMN * DIMN)     /* 1M  */
#define TOT  ((size_t)NB * MATS)       /* 16M */

// ---------------- scratch (device globals; allocation-free) ----------------
__device__ __nv_bfloat16 g_a1h[TOT],  g_a1l[TOT];     // a1 row-major split
__device__ __nv_bfloat16 g_a2h[TOT],  g_a2l[TOT];     // a2 row-major split
__device__ __nv_bfloat16 g_gwh[MATS], g_gwl[MATS];
__device__ __nv_bfloat16 g_a2ph[TOT], g_a2pl[TOT];
__device__ float         g_S[TOT];
__device__ __nv_bfloat16 g_A1h[TOT],  g_A1l[TOT];     // rowsoftmax(S) [l][k]
__device__ __nv_bfloat16 g_A2h[TOT],  g_A2l[TOT];     // colsoftmax(S) [l][k] (NOT transposed)
__device__ float g_rmax[NB * DIMN], g_rinv[NB * DIMN];
__device__ float g_cmax[NB * DIMN], g_cinv[NB * DIMN];
__device__ float g_rpm[NB * 8 * DIMN], g_rps[NB * 8 * DIMN];
__device__ float g_cpm[NB * 8 * DIMN], g_cps[NB * 8 * DIMN];

// ---------------- helpers ----------------
__device__ __forceinline__ unsigned smem_u32(const void* p) {
    unsigned r;
    asm("{ .reg .u64 t; cvta.to.shared.u64 t, %1; cvt.u32.u64 %0, t; }"
        : "=r"(r) : "l"(p));
    return r;
}
__device__ __forceinline__ unsigned swz64(unsigned x)  { return x ^ ((x >> 3) & 0x30); }
__device__ __forceinline__ unsigned swz256(unsigned x) { return x ^ ((x >> 4) & 0x70); }

__device__ __forceinline__ void bsplit(float v, __nv_bfloat16& h, __nv_bfloat16& l) {
    h = __float2bfloat16_rn(v);
    l = __float2bfloat16_rn(v - __bfloat162float(h));
}

#define CP16(dst, src) \
    asm volatile("cp.async.cg.shared.global [%0], [%1], 16;" :: "r"(dst), "l"(src))

#define LDSM4(r, addr) \
    asm volatile("ldmatrix.sync.aligned.m8n8.x4.shared.b16 {%0,%1,%2,%3}, [%4];" \
        : "=r"((r)[0]), "=r"((r)[1]), "=r"((r)[2]), "=r"((r)[3]) : "r"(addr))

#define LDSM4T(r, addr) \
    asm volatile("ldmatrix.sync.aligned.m8n8.x4.trans.shared.b16 {%0,%1,%2,%3}, [%4];" \
        : "=r"((r)[0]), "=r"((r)[1]), "=r"((r)[2]), "=r"((r)[3]) : "r"(addr))

#define MMA16816(c, a, b)                                                      \
    asm volatile("mma.sync.aligned.m16n8k16.row.col.f32.bf16.bf16.f32 "        \
        "{%0,%1,%2,%3}, {%4,%5,%6,%7}, {%8,%9}, {%0,%1,%2,%3};"                \
        : "+f"((c)[0]), "+f"((c)[1]), "+f"((c)[2]), "+f"((c)[3])               \
        : "r"((a)[0]), "r"((a)[1]), "r"((a)[2]), "r"((a)[3]),                  \
          "r"((b)[0]), "r"((b)[1]))

// ================= GEMM cores: CTA 128x128, BK=32, 3-stage, 256 thr =======
#define STAGE_B   32768
#define SMEM_TOT  (3 * STAGE_B)

// ---------- NT core (a2p, S): A,B both K-major (64B rows) ----------
struct GPtr { const char *ah, *al, *bh, *bl; };

__device__ __forceinline__ void issue_loads_s(unsigned st, const GPtr& p, unsigned kbyte,
                                              unsigned so0, unsigned so1) {
    const unsigned RS = 64u * DIMN * 2u;
    CP16(st +     0 + so0, p.ah + kbyte);
    CP16(st +     0 + so1, p.ah + kbyte + RS);
    CP16(st +  8192 + so0, p.al + kbyte);
    CP16(st +  8192 + so1, p.al + kbyte + RS);
    CP16(st + 16384 + so0, p.bh + kbyte);
    CP16(st + 16384 + so1, p.bh + kbyte + RS);
    CP16(st + 24576 + so0, p.bl + kbyte);
    CP16(st + 24576 + so1, p.bl + kbyte + RS);
    asm volatile("cp.async.commit_group;" ::: "memory");
}

__device__ __forceinline__ void mma_stage(unsigned st, int lane, int wm, int wn,
                                          float (*acc)[4][4])
{
#pragma unroll
    for (int ks = 0; ks < 2; ks++) {
        const unsigned kb = ks * 32;
        unsigned bh[8], bl[8];
#pragma unroll
        for (int nt = 0; nt < 2; nt++) {
            unsigned brow = wn + nt * 16 + (lane & 7) + ((lane >> 4) & 1) * 8;
            unsigned bb   = kb + ((lane >> 3) & 1) * 16;
            unsigned ba   = st + 16384 + swz64(brow * 64 + bb);
            LDSM4(bh + nt * 4, ba);
            LDSM4(bl + nt * 4, ba + 8192);
        }
#pragma unroll
        for (int mf = 0; mf < 4; mf++) {
            unsigned arow = wm + mf * 16 + (lane & 15);
            unsigned ab   = kb + ((lane >> 4) & 1) * 16;
            unsigned aa   = st + swz64(arow * 64 + ab);
            unsigned ah[4], al[4];
            LDSM4(ah, aa);
            LDSM4(al, aa + 8192);
#pragma unroll
            for (int nf = 0; nf < 4; nf++) {
                MMA16816(acc[mf][nf], ah, bh + nf * 2);
                MMA16816(acc[mf][nf], ah, bl + nf * 2);
                MMA16816(acc[mf][nf], al, bh + nf * 2);
            }
        }
    }
}

__device__ __forceinline__ void mainloop_s(unsigned sb, const GPtr& p,
                                           unsigned so0, unsigned so1,
                                           int lane, int wm, int wn,
                                           float (*acc)[4][4])
{
    issue_loads_s(sb,           p, 0,  so0, so1);
    issue_loads_s(sb + STAGE_B, p, 64, so0, so1);

#pragma unroll 3
    for (int it = 0; it < 32; it++) {
        if (it < 31) asm volatile("cp.async.wait_group 1;" ::: "memory");
        else         asm volatile("cp.async.wait_group 0;" ::: "memory");
        __syncthreads();
        if (it + 2 < 32) {
            unsigned wst = sb + (unsigned)((it + 2) % 3) * STAGE_B;
            issue_loads_s(wst, p, (unsigned)(it + 2) * 64, so0, so1);
        }
        mma_stage(sb + (unsigned)(it % 3) * STAGE_B, lane, wm, wn, acc);
    }
}

__device__ __forceinline__ void make_gptr(GPtr& p, unsigned& so0, unsigned& so1,
    const __nv_bfloat16* Ah, const __nv_bfloat16* Al,
    const __nv_bfloat16* Bh, const __nv_bfloat16* Bl,
    size_t zA, size_t zB, size_t row0, size_t col0, int tid)
{
    size_t ar = row0 + (tid >> 2);
    size_t br = col0 + (tid >> 2);
    size_t ko = (size_t)(tid & 3) * 8;
    p.ah = (const char*)Ah + (zA + ar * DIMN + ko) * 2;
    p.al = (const char*)Al + (zA + ar * DIMN + ko) * 2;
    p.bh = (const char*)Bh + (zB + br * DIMN + ko) * 2;
    p.bl = (const char*)Bl + (zB + br * DIMN + ko) * 2;
    so0 = swz64(((unsigned)(tid >> 2)) * 64 + (tid & 3) * 16);
    so1 = so0 + 4096;
}

// ---- a2p GEMM: bias add + split bf16 pair out ----
__global__ __launch_bounds__(256, 2)
void gemm_a2p(const __nv_bfloat16* __restrict__ Ah, const __nv_bfloat16* __restrict__ Al,
              const __nv_bfloat16* __restrict__ Bh, const __nv_bfloat16* __restrict__ Bl,
              __nv_bfloat16* __restrict__ outH, __nv_bfloat16* __restrict__ outL,
              const float* __restrict__ bias)
{
    extern __shared__ char smem[];
    const unsigned sb = smem_u32(smem);
    const int tid = threadIdx.x, warp = tid >> 5, lane = tid & 31;
    const int wm = (warp >> 2) * 64, wn = (warp & 3) * 32;
    const size_t row0 = (size_t)blockIdx.y * 128, col0 = (size_t)blockIdx.x * 128;

    GPtr p; unsigned so0, so1;
    make_gptr(p, so0, so1, Ah, Al, Bh, Bl, 0, 0, row0, col0, tid);
    float acc[4][4][4] = {};
    mainloop_s(sb, p, so0, so1, lane, wm, wn, acc);

    const int g = lane >> 2, t = lane & 3;
#pragma unroll
    for (int mf = 0; mf < 4; mf++)
#pragma unroll
        for (int nf = 0; nf < 4; nf++) {
            const float* c = acc[mf][nf];
            size_t r0 = row0 + wm + mf * 16 + g;
            size_t cc = col0 + wn + nf * 8 + 2 * t;
            float b0 = bias[cc], b1 = bias[cc + 1];
            union { __nv_bfloat16 b[2]; unsigned u; } H0, L0, H1, L1;
            bsplit(c[0] + b0, H0.b[0], L0.b[0]);
            bsplit(c[1] + b1, H0.b[1], L0.b[1]);
            bsplit(c[2] + b0, H1.b[0], L1.b[0]);
            bsplit(c[3] + b1, H1.b[1], L1.b[1]);
            *(unsigned*)(outH + r0 * DIMN + cc)       = H0.u;
            *(unsigned*)(outL + r0 * DIMN + cc)       = L0.u;
            *(unsigned*)(outH + (r0 + 8) * DIMN + cc) = H1.u;
            *(unsigned*)(outL + (r0 + 8) * DIMN + cc) = L1.u;
        }
}

// ---- S GEMM: fp32 out + fused per-CTA row/col softmax partials ----
__global__ __launch_bounds__(256, 2)
void gemm_S(const __nv_bfloat16* __restrict__ Ah, const __nv_bfloat16* __restrict__ Al,
            const __nv_bfloat16* __restrict__ Bh, const __nv_bfloat16* __restrict__ Bl,
            float* __restrict__ outF,
            float* __restrict__ rpm, float* __restrict__ rps,
            float* __restrict__ cpm, float* __restrict__ cps)
{
    extern __shared__ char smem[];
    const unsigned sb = smem_u32(smem);
    const int tid = threadIdx.x, warp = tid >> 5, lane = tid & 31;
    const int wm = (warp >> 2) * 64, wn = (warp & 3) * 32;
    const size_t z = blockIdx.z;
    const size_t row0 = (size_t)blockIdx.y * 128, col0 = (size_t)blockIdx.x * 128;

    GPtr p; unsigned so0, so1;
    make_gptr(p, so0, so1, Ah, Al, Bh, Bl, z * MATS, z * MATS, row0, col0, tid);
    float acc[4][4][4] = {};
    mainloop_s(sb, p, so0, so1, lane, wm, wn, acc);

    const int g = lane >> 2, t = lane & 3;
    float* outb = outF + z * MATS;
#pragma unroll
    for (int mf = 0; mf < 4; mf++)
#pragma unroll
        for (int nf = 0; nf < 4; nf++) {
            const float* c = acc[mf][nf];
            size_t r0 = row0 + wm + mf * 16 + g;
            size_t cc = col0 + wn + nf * 8 + 2 * t;
            *(float2*)(outb + r0 * DIMN + cc)       = make_float2(c[0], c[1]);
            *(float2*)(outb + (r0 + 8) * DIMN + cc) = make_float2(c[2], c[3]);
        }

    // ---- softmax partials from registers ----
    float rm_[4][2], rs_[4][2];
#pragma unroll
    for (int mf = 0; mf < 4; mf++)
#pragma unroll
        for (int rh = 0; rh < 2; rh++) {
            float m = -1e30f;
#pragma unroll
            for (int nf = 0; nf < 4; nf++)
                m = fmaxf(m, fmaxf(acc[mf][nf][rh * 2], acc[mf][nf][rh * 2 + 1]));
            m = fmaxf(m, __shfl_xor_sync(0xffffffffu, m, 1));
            m = fmaxf(m, __shfl_xor_sync(0xffffffffu, m, 2));
            float s = 0.f;
#pragma unroll
            for (int nf = 0; nf < 4; nf++)
                s += __expf(acc[mf][nf][rh * 2] - m) + __expf(acc[mf][nf][rh * 2 + 1] - m);
            s += __shfl_xor_sync(0xffffffffu, s, 1);
            s += __shfl_xor_sync(0xffffffffu, s, 2);
            rm_[mf][rh] = m; rs_[mf][rh] = s;
        }
    float cm_[4][2], cs_[4][2];
#pragma unroll
    for (int nf = 0; nf < 4; nf++)
#pragma unroll
        for (int cr = 0; cr < 2; cr++) {
            float m = -1e30f;
#pragma unroll
            for (int mf = 0; mf < 4; mf++)
                m = fmaxf(m, fmaxf(acc[mf][nf][cr], acc[mf][nf][2 + cr]));
            m = fmaxf(m, __shfl_xor_sync(0xffffffffu, m, 4));
            m = fmaxf(m, __shfl_xor_sync(0xffffffffu, m, 8));
            m = fmaxf(m, __shfl_xor_sync(0xffffffffu, m, 16));
            float s = 0.f;
#pragma unroll
            for (int mf = 0; mf < 4; mf++)
                s += __expf(acc[mf][nf][cr] - m) + __expf(acc[mf][nf][2 + cr] - m);
            s += __shfl_xor_sync(0xffffffffu, s, 4);
            s += __shfl_xor_sync(0xffffffffu, s, 8);
            s += __shfl_xor_sync(0xffffffffu, s, 16);
            cm_[nf][cr] = m; cs_[nf][cr] = s;
        }

    __syncthreads();   // stage buffers dead; reuse smem for staging
    float* sRM = (float*)smem;        // [4][128]
    float* sRS = sRM + 512;
    float* sCM = sRS + 512;           // [2][128]
    float* sCS = sCM + 256;
    if (t == 0) {
#pragma unroll
        for (int mf = 0; mf < 4; mf++)
#pragma unroll
            for (int rh = 0; rh < 2; rh++) {
                int r = wm + mf * 16 + g + 8 * rh;
                sRM[(warp & 3) * 128 + r] = rm_[mf][rh];
                sRS[(warp & 3) * 128 + r] = rs_[mf][rh];
            }
    }
    if (g == 0) {
#pragma unroll
        for (int nf = 0; nf < 4; nf++)
#pragma unroll
            for (int cr = 0; cr < 2; cr++) {
                int c = wn + nf * 8 + 2 * t + cr;
                sCM[(warp >> 2) * 128 + c] = cm_[nf][cr];
                sCS[(warp >> 2) * 128 + c] = cs_[nf][cr];
            }
    }
    __syncthreads();
    if (tid < 128) {
        int r = tid;
        float m = -1e30f;
#pragma unroll
        for (int w = 0; w < 4; w++) m = fmaxf(m, sRM[w * 128 + r]);
        float s = 0.f;
#pragma unroll
        for (int w = 0; w < 4; w++) s += sRS[w * 128 + r] * __expf(sRM[w * 128 + r] - m);
        size_t ri = (z * DIMN + row0 + r) * 8 + blockIdx.x;
        rpm[ri] = m; rps[ri] = s;

        int c = tid;
        float mc = fmaxf(sCM[c], sCM[128 + c]);
        float sc = sCS[c] * __expf(sCM[c] - mc) + sCS[128 + c] * __expf(sCM[128 + c] - mc);
        size_t ci = (z * DIMN + col0 + c) * 8 + blockIdx.y;
        cpm[ci] = mc; cps[ci] = sc;
    }
}

// ---------- M1 GEMM: A normal (A1 [l][k]), B trans from a2 [k][d] ----------
__global__ __launch_bounds__(256, 2)
void gemm_m1(const __nv_bfloat16* __restrict__ Ah, const __nv_bfloat16* __restrict__ Al,
             const __nv_bfloat16* __restrict__ Bh, const __nv_bfloat16* __restrict__ Bl,
             float* __restrict__ o)
{
    extern __shared__ char smem[];
    const unsigned sb = smem_u32(smem);
    const int tid = threadIdx.x, warp = tid >> 5, lane = tid & 31;
    const int wm = (warp >> 2) * 64, wn = (warp & 3) * 32;
    const size_t z = blockIdx.z;
    const size_t row0 = (size_t)blockIdx.y * 128, col0 = (size_t)blockIdx.x * 128;

    // A pointers: [m][k] 64B rows
    size_t ar = row0 + (tid >> 2);
    size_t ko = (size_t)(tid & 3) * 8;
    const char* pAh = (const char*)Ah + (z * MATS + ar * DIMN + ko) * 2;
    const char* pAl = (const char*)Al + (z * MATS + ar * DIMN + ko) * 2;
    const unsigned so0 = swz64(((unsigned)(tid >> 2)) * 64 + (tid & 3) * 16);
    const unsigned so1 = so0 + 4096;
    // B pointers: [k][n] 256B rows (32 k-rows per stage)
    size_t brr = (size_t)(tid >> 3);
    size_t bcc = col0 + (size_t)(tid & 7) * 16;
    const char* pBh = (const char*)Bh + (z * MATS + brr * DIMN + bcc) * 2;
    const char* pBl = (const char*)Bl + (z * MATS + brr * DIMN + bcc) * 2;
    const unsigned sB0 = swz256(((unsigned)(tid >> 3)) * 256 + (tid & 7) * 32);
    const unsigned sB1 = swz256(((unsigned)(tid >> 3)) * 256 + (tid & 7) * 32 + 16);
    const unsigned RSA = 64u * DIMN * 2u;
    const unsigned RSB = 32u * DIMN * 2u;

    float acc[4][4][4] = {};

#define M1_ISSUE(st, it) do {                                                   \
    unsigned ka = (unsigned)(it) * 64u, kb8 = (unsigned)(it) * RSB;             \
    CP16((st) +     0 + so0, pAh + ka);                                         \
    CP16((st) +     0 + so1, pAh + ka + RSA);                                   \
    CP16((st) +  8192 + so0, pAl + ka);                                         \
    CP16((st) +  8192 + so1, pAl + ka + RSA);                                   \
    CP16((st) + 16384 + sB0, pBh + kb8);                                        \
    CP16((st) + 16384 + sB1, pBh + kb8 + 16);                                   \
    CP16((st) + 24576 + sB0, pBl + kb8);                                        \
    CP16((st) + 24576 + sB1, pBl + kb8 + 16);                                   \
    asm volatile("cp.async.commit_group;" ::: "memory");                        \
} while (0)

    M1_ISSUE(sb, 0);
    M1_ISSUE(sb + STAGE_B, 1);

#pragma unroll 1
    for (int it = 0; it < 32; it++) {
        if (it < 31) asm volatile("cp.async.wait_group 1;" ::: "memory");
        else         asm volatile("cp.async.wait_group 0;" ::: "memory");
        __syncthreads();
        if (it + 2 < 32) M1_ISSUE(sb + (unsigned)((it + 2) % 3) * STAGE_B, it + 2);
        const unsigned st = sb + (unsigned)(it % 3) * STAGE_B;

#pragma unroll
        for (int ks = 0; ks < 2; ks++) {
            const unsigned kel = ks * 16;
            unsigned bh[8], bl[8];
#pragma unroll
            for (int nt = 0; nt < 2; nt++) {
                unsigned krow = kel + (lane & 7) + ((lane >> 3) & 1) * 8;
                unsigned ncol = wn + nt * 16 + ((lane >> 4) & 1) * 8;
                unsigned ba   = st + 16384 + swz256(krow * 256 + ncol * 2);
                LDSM4T(bh + nt * 4, ba);
                LDSM4T(bl + nt * 4, ba + 8192);
            }
#pragma unroll
            for (int mf = 0; mf < 4; mf++) {
                unsigned arow = wm + mf * 16 + (lane & 15);
                unsigned ab   = ks * 32 + ((lane >> 4) & 1) * 16;
                unsigned aa   = st + swz64(arow * 64 + ab);
                unsigned ah[4], al[4];
                LDSM4(ah, aa);
                LDSM4(al, aa + 8192);
#pragma unroll
                for (int nf = 0; nf < 4; nf++) {
                    MMA16816(acc[mf][nf], ah, bh + nf * 2);
                    MMA16816(acc[mf][nf], ah, bl + nf * 2);
                    MMA16816(acc[mf][nf], al, bh + nf * 2);
                }
            }
        }
    }
#undef M1_ISSUE

    const int g = lane >> 2, t = lane & 3;
    float* outb = o + z * MATS;
#pragma unroll
    for (int mf = 0; mf < 4; mf++)
#pragma unroll
        for (int nf = 0; nf < 4; nf++) {
            const float* c = acc[mf][nf];
            size_t r0 = row0 + wm + mf * 16 + g;
            size_t cc = col0 + wn + nf * 8 + 2 * t;
            *(float2*)(outb + r0 * DIMN + cc)       = make_float2(c[0], c[1]);
            *(float2*)(outb + (r0 + 8) * DIMN + cc) = make_float2(c[2], c[3]);
        }
}

// ---------- M2 GEMM: A trans from A2 [l][k], B trans from a1 [l][d] ----------
__global__ __launch_bounds__(256, 2)
void gemm_m2(const __nv_bfloat16* __restrict__ Ah, const __nv_bfloat16* __restrict__ Al,
             const __nv_bfloat16* __restrict__ Bh, const __nv_bfloat16* __restrict__ Bl,
             float* __restrict__ o)
{
    extern __shared__ char smem[];
    const unsigned sb = smem_u32(smem);
    const int tid = threadIdx.x, warp = tid >> 5, lane = tid & 31;
    const int wm = (warp >> 2) * 64, wn = (warp & 3) * 32;
    const size_t z = blockIdx.z;
    const size_t row0 = (size_t)blockIdx.y * 128, col0 = (size_t)blockIdx.x * 128;

    // A: [l][m] 256B rows, cols row0..row0+127
    size_t lr = (size_t)(tid >> 3);
    size_t ac = row0 + (size_t)(tid & 7) * 16;
    const char* pAh = (const char*)Ah + (z * MATS + lr * DIMN + ac) * 2;
    const char* pAl = (const char*)Al + (z * MATS + lr * DIMN + ac) * 2;
    // B: [l][n] 256B rows, cols col0..col0+127
    size_t bc = col0 + (size_t)(tid & 7) * 16;
    const char* pBh = (const char*)Bh + (z * MATS + lr * DIMN + bc) * 2;
    const char* pBl = (const char*)Bl + (z * MATS + lr * DIMN + bc) * 2;
    const unsigned sT0 = swz256(((unsigned)(tid >> 3)) * 256 + (tid & 7) * 32);
    const unsigned sT1 = swz256(((unsigned)(tid >> 3)) * 256 + (tid & 7) * 32 + 16);
    const unsigned RSB = 32u * DIMN * 2u;

    float acc[4][4][4] = {};

#define M2_ISSUE(st, it) do {                                                   \
    unsigned kk = (unsigned)(it) * RSB;                                         \
    CP16((st) +     0 + sT0, pAh + kk);                                         \
    CP16((st) +     0 + sT1, pAh + kk + 16);                                    \
    CP16((st) +  8192 + sT0, pAl + kk);                                         \
    CP16((st) +  8192 + sT1, pAl + kk + 16);                                    \
    CP16((st) + 16384 + sT0, pBh + kk);                                         \
    CP16((st) + 16384 + sT1, pBh + kk + 16);                                    \
    CP16((st) + 24576 + sT0, pBl + kk);                                         \
    CP16((st) + 24576 + sT1, pBl + kk + 16);                                    \
    asm volatile("cp.async.commit_group;" ::: "memory");                        \
} while (0)

    M2_ISSUE(sb, 0);
    M2_ISSUE(sb + STAGE_B, 1);

#pragma unroll 1
    for (int it = 0; it < 32; it++) {
        if (it < 31) asm volatile("cp.async.wait_group 1;" ::: "memory");
        else         asm volatile("cp.async.wait_group 0;" ::: "memory");
        __syncthreads();
        if (it + 2 < 32) M2_ISSUE(sb + (unsigned)((it + 2) % 3) * STAGE_B, it + 2);
        const unsigned st = sb + (unsigned)(it % 3) * STAGE_B;

#pragma unroll
        for (int ks = 0; ks < 2; ks++) {
            const unsigned kel = ks * 16;
            unsigned bh[8], bl[8];
#pragma unroll
            for (int nt = 0; nt < 2; nt++) {
                unsigned krow = kel + (lane & 7) + ((lane >> 3) & 1) * 8;
                unsigned ncol = wn + nt * 16 + ((lane >> 4) & 1) * 8;
                unsigned ba   = st + 16384 + swz256(krow * 256 + ncol * 2);
                LDSM4T(bh + nt * 4, ba);
                LDSM4T(bl + nt * 4, ba + 8192);
            }
#pragma unroll
            for (int mf = 0; mf < 4; mf++) {
                unsigned krow = kel + (lane & 7) + ((lane >> 4) & 1) * 8;
                unsigned mcol = wm + mf * 16 + ((lane >> 3) & 1) * 8;
                unsigned aa   = st + swz256(krow * 256 + mcol * 2);
                unsigned ah[4], al[4];
                LDSM4T(ah, aa);
                LDSM4T(al, aa + 8192);
#pragma unroll
                for (int nf = 0; nf < 4; nf++) {
                    MMA16816(acc[mf][nf], ah, bh + nf * 2);
                    MMA16816(acc[mf][nf], ah, bl + nf * 2);
                    MMA16816(acc[mf][nf], al, bh + nf * 2);
                }
            }
        }
    }
#undef M2_ISSUE

    const int g = lane >> 2, t = lane & 3;
    float* outb = o + z * MATS;
#pragma unroll
    for (int mf = 0; mf < 4; mf++)
#pragma unroll
        for (int nf = 0; nf < 4; nf++) {
            const float* c = acc[mf][nf];
            size_t r0 = row0 + wm + mf * 16 + g;
            size_t cc = col0 + wn + nf * 8 + 2 * t;
            *(float2*)(outb + r0 * DIMN + cc)       = make_float2(c[0], c[1]);
            *(float2*)(outb + (r0 + 8) * DIMN + cc) = make_float2(c[2], c[3]);
        }
}

// ---------------- elementwise ----------------
__global__ __launch_bounds__(256)
void split_kernel(const float* __restrict__ in, __nv_bfloat16* __restrict__ h,
                  __nv_bfloat16* __restrict__ l)
{
    size_t i = (size_t)blockIdx.x * 256 + threadIdx.x;
    float4 v = ((const float4*)in)[i];
    union { __nv_bfloat16 b[4]; uint2 u; } H, L;
    bsplit(v.x, H.b[0], L.b[0]); bsplit(v.y, H.b[1], L.b[1]);
    bsplit(v.z, H.b[2], L.b[2]); bsplit(v.w, H.b[3], L.b[3]);
    ((uint2*)h)[i] = H.u;
    ((uint2*)l)[i] = L.u;
}

// combine 8 (max,sum) partials -> (max, 1/sum)
__global__ __launch_bounds__(256)
void combine_kernel(const float* __restrict__ pm, const float* __restrict__ ps,
                    float* __restrict__ omax, float* __restrict__ oinv)
{
    int idx = blockIdx.x * 256 + threadIdx.x;
    const float* m8 = pm + (size_t)idx * 8;
    const float* s8 = ps + (size_t)idx * 8;
    float m = -1e30f;
#pragma unroll
    for (int j = 0; j < 8; j++) m = fmaxf(m, m8[j]);
    float s = 0.f;
#pragma unroll
    for (int j = 0; j < 8; j++) s += s8[j] * __expf(m8[j] - m);
    omax[idx] = m;
    oinv[idx] = 1.0f / s;
}

// A1 = rowsoftmax(S) split (row-major, coalesced)
__global__ __launch_bounds__(256)
void apply_row(const float* __restrict__ S,
               const float* __restrict__ rmax, const float* __restrict__ rinv,
               __nv_bfloat16* __restrict__ A1h, __nv_bfloat16* __restrict__ A1l)
{
    size_t i = (size_t)blockIdx.x * 256 + threadIdx.x;   // float4 units
    int row = (int)(i >> 8);
    float rm = rmax[row], ri = rinv[row];
    float4 v = ((const float4*)S)[i];
    union { __nv_bfloat16 b[4]; uint2 u; } H, L;
    bsplit(__expf(v.x - rm) * ri, H.b[0], L.b[0]);
    bsplit(__expf(v.y - rm) * ri, H.b[1], L.b[1]);
    bsplit(__expf(v.z - rm) * ri, H.b[2], L.b[2]);
    bsplit(__expf(v.w - rm) * ri, H.b[3], L.b[3]);
    ((uint2*)A1h)[i] = H.u;
    ((uint2*)A1l)[i] = L.u;
}

// A2 = colsoftmax(S) split, row-major [l][k] (coalesced; stats indexed by k)
__global__ __launch_bounds__(256)
void apply_col(const float* __restrict__ S,
               const float* __restrict__ cmax, const float* __restrict__ cinv,
               __nv_bfloat16* __restrict__ A2h, __nv_bfloat16* __restrict__ A2l)
{
    size_t i = (size_t)blockIdx.x * 256 + threadIdx.x;   // float4 units over group
    int zi = (int)(i >> 18);                              // batch within group
    int k4 = (int)(i & 255) * 4;
    const float4 cm = *(const float4*)(cmax + zi * DIMN + k4);
    const float4 ci = *(const float4*)(cinv + zi * DIMN + k4);
    float4 v = ((const float4*)S)[i];
    union { __nv_bfloat16 b[4]; uint2 u; } H, L;
    bsplit(__expf(v.x - cm.x) * ci.x, H.b[0], L.b[0]);
    bsplit(__expf(v.y - cm.y) * ci.y, H.b[1], L.b[1]);
    bsplit(__expf(v.z - cm.z) * ci.z, H.b[2], L.b[2]);
    bsplit(__expf(v.w - cm.w) * ci.w, H.b[3], L.b[3]);
    ((uint2*)A2h)[i] = H.u;
    ((uint2*)A2l)[i] = L.u;
}

// ---------------- capture-DAG helpers ----------------
static inline cudaGraphNode_t cap_tail() {
    cudaStreamCaptureStatus st = cudaStreamCaptureStatusNone;
    unsigned long long id = 0;
    cudaGraph_t gr = nullptr;
    const cudaGraphNode_t* deps = nullptr;
    const cudaGraphEdgeData* edges = nullptr;
    size_t nd = 0;
    cudaError_t e = cudaStreamGetCaptureInfo((cudaStream_t)0, &st, &id, &gr,
                                             &deps, &edges, &nd);
    if (e != cudaSuccess || st != cudaStreamCaptureStatusActive || nd < 1) {
        (void)cudaGetLastError();
        return nullptr;
    }
    return deps[nd - 1];
}
static inline void cap_set_deps(cudaGraphNode_t* nodes, size_t n) {
    if (!nodes || !nodes[0]) { (void)cudaGetLastError(); return; }
    (void)cudaStreamUpdateCaptureDependencies((cudaStream_t)0, nodes,
                                              (const cudaGraphEdgeData*)nullptr, n,
                                              cudaStreamSetCaptureDependencies);
    (void)cudaGetLastError();
}

// ---------------- launcher ----------------
extern "C" void kernel_launch(void* const* d_in, const int* in_sizes, int n_in,
                              void* d_out, int out_size)
{
    const float* a1 = (const float*)d_in[0];
    const float* a2 = (const float*)d_in[1];
    const float* Gw = (const float*)d_in[2];
    const float* Gb = (const float*)d_in[3];
    float* M1 = (float*)d_out;
    float* M2 = M1 + TOT;

    __nv_bfloat16 *a1h, *a1l, *a2h, *a2l, *gwh, *gwl, *a2ph, *a2pl;
    __nv_bfloat16 *A1h, *A1l, *A2h, *A2l;
    float *S, *rmax, *rinv, *cmax, *cinv, *rpm, *rps, *cpm, *cps;
    cudaGetSymbolAddress((void**)&a1h, g_a1h);   cudaGetSymbolAddress((void**)&a1l, g_a1l);
    cudaGetSymbolAddress((void**)&a2h, g_a2h);   cudaGetSymbolAddress((void**)&a2l, g_a2l);
    cudaGetSymbolAddress((void**)&gwh, g_gwh);   cudaGetSymbolAddress((void**)&gwl, g_gwl);
    cudaGetSymbolAddress((void**)&a2ph, g_a2ph); cudaGetSymbolAddress((void**)&a2pl, g_a2pl);
    cudaGetSymbolAddress((void**)&A1h, g_A1h);   cudaGetSymbolAddress((void**)&A1l, g_A1l);
    cudaGetSymbolAddress((void**)&A2h, g_A2h);   cudaGetSymbolAddress((void**)&A2l, g_A2l);
    cudaGetSymbolAddress((void**)&S, g_S);
    cudaGetSymbolAddress((void**)&rmax, g_rmax); cudaGetSymbolAddress((void**)&rinv, g_rinv);
    cudaGetSymbolAddress((void**)&cmax, g_cmax); cudaGetSymbolAddress((void**)&cinv, g_cinv);
    cudaGetSymbolAddress((void**)&rpm, g_rpm);   cudaGetSymbolAddress((void**)&rps, g_rps);
    cudaGetSymbolAddress((void**)&cpm, g_cpm);   cudaGetSymbolAddress((void**)&cps, g_cps);

    cudaFuncSetAttribute(gemm_a2p, cudaFuncAttributeMaxDynamicSharedMemorySize, SMEM_TOT);
    cudaFuncSetAttribute(gemm_S,   cudaFuncAttributeMaxDynamicSharedMemorySize, SMEM_TOT);
    cudaFuncSetAttribute(gemm_m1,  cudaFuncAttributeMaxDynamicSharedMemorySize, SMEM_TOT);
    cudaFuncSetAttribute(gemm_m2,  cudaFuncAttributeMaxDynamicSharedMemorySize, SMEM_TOT);

    // root: Gw split (fork point for all 4 chains)
    split_kernel<<<1024, 256>>>(Gw, gwh, gwl);
    cudaGraphNode_t nGw = cap_tail();

    cudaGraphNode_t nTail[8] = {};
    for (int grp = 0; grp < 4; grp++) {
        const size_t mo = (size_t)grp * 4 * MATS;      // matrix offset (4 batches)
        const size_t vo = (size_t)grp * 4 * DIMN;      // vector offset
        const size_t po = vo * 8;                       // partials offset

        // fork: splits depend only on the Gw node
        cap_set_deps(&nGw, 1);
        split_kernel<<<4096, 256>>>(a2 + mo, a2h + mo, a2l + mo);
        cudaGraphNode_t nF2 = cap_tail();

        cap_set_deps(&nGw, 1);
        split_kernel<<<4096, 256>>>(a1 + mo, a1h + mo, a1l + mo);
        cudaGraphNode_t nF1 = cap_tail();

        // a2p depends on split(a2)
        cap_set_deps(&nF2, 1);
        gemm_a2p<<<dim3(8, 32, 1), 256, SMEM_TOT>>>(
            a2h + mo, a2l + mo, gwh, gwl, a2ph + mo, a2pl + mo, Gb);
        cudaGraphNode_t nA2p = cap_tail();

        // S depends on split(a1) + a2p
        {
            cudaGraphNode_t d2[2] = { nF1, nA2p };
            cap_set_deps(d2, (nF1 && nA2p) ? 2 : 1);
        }
        gemm_S<<<dim3(8, 8, 4), 256, SMEM_TOT>>>(
            a1h + mo, a1l + mo, a2ph + mo, a2pl + mo, S + mo,
            rpm + po, rps + po, cpm + po, cps + po);
        cudaGraphNode_t nS = cap_tail();

        // --- row path: combine_r -> applyA1 -> gemm M1 (B = a2 row-major) ---
        combine_kernel<<<16, 256>>>(rpm + po, rps + po, rmax + vo, rinv + vo);
        apply_row<<<4096, 256>>>(S + mo, rmax + vo, rinv + vo, A1h + mo, A1l + mo);
        gemm_m1<<<dim3(8, 8, 4), 256, SMEM_TOT>>>(
            A1h + mo, A1l + mo, a2h + mo, a2l + mo, M1 + mo);
        nTail[grp * 2] = cap_tail();

        // --- col path: combine_c -> applyA2 -> gemm M2 (fork from S) ---
        cap_set_deps(&nS, 1);
        combine_kernel<<<16, 256>>>(cpm + po, cps + po, cmax + vo, cinv + vo);
        apply_col<<<4096, 256>>>(S + mo, cmax + vo, cinv + vo, A2h + mo, A2l + mo);
        gemm_m2<<<dim3(8, 8, 4), 256, SMEM_TOT>>>(
            A2h + mo, A2l + mo, a1h + mo, a1l + mo, M2 + mo);
        nTail[grp * 2 + 1] = cap_tail();
    }

    // join
    bool all = true;
    for (int i = 0; i < 8; i++) all = all && (nTail[i] != nullptr);
    if (all) cap_set_deps(nTail, 8);
}